// round 11
// baseline (speedup 1.0000x reference)
#include <cuda_runtime.h>
#include <cuda_bf16.h>
#include <cuda_fp16.h>
#include <math.h>
#include <stdint.h>

// ---------------------------------------------------------------------------
// Problem constants
// ---------------------------------------------------------------------------
#define NMAX 50000
#define EMAX 800000

// ---------------------------------------------------------------------------
// Scratch (device globals)
// ---------------------------------------------------------------------------
__device__ __half g_h16 [(size_t)NMAX * 128];  // gat chain Wh (fp16, agg-only)
__device__ __half g_hq16[(size_t)NMAX * 64];   // pg chain Wh (fp16, agg-only)
__device__ float g_rh [(size_t)NMAX * 128];    // gat chain rWh (fp32 residual)
__device__ float g_hs [(size_t)NMAX * 128];
__device__ float g_hs2[(size_t)NMAX * 128];
__device__ float g_hp [(size_t)NMAX * 64];
__device__ float g_el [(size_t)NMAX * 2];
__device__ float g_er [(size_t)NMAX * 2];
__device__ float g_el2[(size_t)NMAX * 2];
__device__ float g_er2[(size_t)NMAX * 2];
__device__ int   g_off[NMAX + 1];
__device__ int   g_cnt[NMAX];
__device__ int   g_esrc[EMAX];

// Fused transposed hi/lo bf16 weights
#define WT_FUSED (256 * 192)
#define WT_SMALL (64 * 64)
__device__ uint16_t g_wthi[3 * WT_FUSED + 2 * WT_SMALL];
__device__ uint16_t g_wtlo[3 * WT_FUSED + 2 * WT_SMALL];

// ---------------------------------------------------------------------------
// Helpers
// ---------------------------------------------------------------------------
__device__ __forceinline__ uint32_t smem_u32(const void* p) {
    uint32_t a;
    asm("{ .reg .u64 t; cvta.to.shared.u64 t, %1; cvt.u32.u64 %0, t; }"
        : "=r"(a) : "l"(p));
    return a;
}

__device__ __forceinline__ void ldsm_x4(uint32_t* r, uint32_t addr) {
    asm volatile("ldmatrix.sync.aligned.m8n8.x4.shared.b16 {%0,%1,%2,%3}, [%4];"
                 : "=r"(r[0]), "=r"(r[1]), "=r"(r[2]), "=r"(r[3]) : "r"(addr));
}

__device__ __forceinline__ void mma16816(float* c, const uint32_t* a, const uint32_t* b) {
    asm volatile(
        "mma.sync.aligned.m16n8k16.row.col.f32.bf16.bf16.f32 "
        "{%0,%1,%2,%3}, {%4,%5,%6,%7}, {%8,%9}, {%0,%1,%2,%3};"
        : "+f"(c[0]), "+f"(c[1]), "+f"(c[2]), "+f"(c[3])
        : "r"(a[0]), "r"(a[1]), "r"(a[2]), "r"(a[3]), "r"(b[0]), "r"(b[1]));
}

__device__ __forceinline__ void cpasync16(uint32_t s, const void* g) {
    asm volatile("cp.async.cg.shared.global [%0], [%1], 16;" :: "r"(s), "l"(g));
}
__device__ __forceinline__ void cpasync_wait() {
    asm volatile("cp.async.commit_group;");
    asm volatile("cp.async.wait_group 0;" ::: "memory");
}

__device__ __forceinline__ void split8(const float* v, uint4& h4, uint4& l4) {
    uint16_t* hp = (uint16_t*)&h4;
    uint16_t* lp = (uint16_t*)&l4;
#pragma unroll
    for (int i = 0; i < 8; i++) {
        __nv_bfloat16 hb = __float2bfloat16(v[i]);
        float r = v[i] - __bfloat162float(hb);
        __nv_bfloat16 lb = __float2bfloat16(r);
        hp[i] = *(uint16_t*)&hb;
        lp[i] = *(uint16_t*)&lb;
    }
}

__device__ __forceinline__ uint32_t swz(int row, int g, int ROWB) {
    int c = (g & ~7) | ((g ^ row) & 7);
    return (uint32_t)(row * ROWB + c * 16);
}

// ---------------------------------------------------------------------------
// Weight prep
// ---------------------------------------------------------------------------
struct Prep8 {
    const float* W[8];
    int K[8], N[8], off[8];
};

__global__ void prep_kernel(Prep8 p) {
    for (int m = 0; m < 8; m++) {
        const int K = p.K[m], N = p.N[m], tot = K * N, off = p.off[m];
        const float* W = p.W[m];
        for (int idx = blockIdx.x * blockDim.x + threadIdx.x; idx < tot;
             idx += gridDim.x * blockDim.x) {
            int n = idx / K, k = idx - n * K;
            float w = W[(size_t)k * N + n];
            __nv_bfloat16 h = __float2bfloat16(w);
            float r = w - __bfloat162float(h);
            __nv_bfloat16 l = __float2bfloat16(r);
            g_wthi[off + idx] = *(uint16_t*)&h;
            g_wtlo[off + idx] = *(uint16_t*)&l;
        }
    }
}

// ---------------------------------------------------------------------------
// Fused bf16x3 GEMM + el/er epilogue (gat chain).
// wn=0 warps -> H16 (fp16 Wh for agg); wn=1 warps -> C2 (fp32 residual).
// ---------------------------------------------------------------------------
template <int K>
__global__ __launch_bounds__(256, 1) void tc_gemm_fused(
    const float* __restrict__ A1, int K1,
    const float* __restrict__ A2,
    const uint16_t* __restrict__ Bh, const uint16_t* __restrict__ Bl,
    const float* __restrict__ al, const float* __restrict__ ar,
    float* __restrict__ el, float* __restrict__ er,
    __half* __restrict__ H16, float* __restrict__ C2, int M)
{
    constexpr int BN   = 256;
    constexpr int ROWB = K * 2;
    constexpr int NG   = K / 8;
    constexpr int WN   = 128;
    constexpr int NT   = WN / 8;
    constexpr int KS   = K / 16;
    constexpr int AOFF  = 0;
    constexpr int ALOFF = 128 * ROWB;
    constexpr int BOFF  = 2 * 128 * ROWB;

    extern __shared__ char smem[];
    const uint32_t sb  = smem_u32(smem);
    const uint32_t sAH = sb + AOFF;
    const uint32_t sAL = sb + ALOFF;
    const uint32_t sB  = sb + BOFF;

    const int t    = threadIdx.x;
    const int wid  = t >> 5;
    const int lane = t & 31;
    const int bm   = blockIdx.x * 128;

    for (int idx = t; idx < BN * NG; idx += 256) {
        int rn = idx / NG, g = idx - rn * NG;
        cpasync16(sB + swz(rn, g, ROWB), Bh + (size_t)rn * K + g * 8);
    }

    for (int idx = t; idx < 128 * NG; idx += 256) {
        int row = idx / NG, g = idx - row * NG, k0 = g * 8;
        int grow = bm + row;
        float v[8] = {0, 0, 0, 0, 0, 0, 0, 0};
        if (grow < M) {
            const float* p = (k0 < K1) ? (A1 + (size_t)grow * K1 + k0)
                                       : (A2 + (size_t)grow * (K - K1) + (k0 - K1));
            *(float4*)&v[0] = ((const float4*)p)[0];
            *(float4*)&v[4] = ((const float4*)p)[1];
        }
        uint4 h4, l4;
        split8(v, h4, l4);
        uint32_t o = swz(row, g, ROWB);
        *(uint4*)(smem + AOFF + o)  = h4;
        *(uint4*)(smem + ALOFF + o) = l4;
    }
    cpasync_wait();
    __syncthreads();

    const int wm   = wid & 3;
    const int wn   = wid >> 2;
    const int lr   = lane & 7;
    const int sel  = lane >> 3;
    const int selb1 = sel & 1;
    const int selb2 = sel >> 1;
    const int rowA_base = wm * 32 + lr + selb1 * 8;
    const int rowB_base = wn * WN + lr + selb2 * 8;

    float acc[2][NT][4];
#pragma unroll
    for (int mt = 0; mt < 2; mt++)
#pragma unroll
        for (int nt = 0; nt < NT; nt++)
#pragma unroll
            for (int q = 0; q < 4; q++) acc[mt][nt][q] = 0.f;

#pragma unroll
    for (int ks = 0; ks < KS; ks++) {
        uint32_t bfr[NT][2];
#pragma unroll
        for (int nt2 = 0; nt2 < NT / 2; nt2++) {
            uint32_t r[4];
            ldsm_x4(r, sB + swz(rowB_base + nt2 * 16, ks * 2 + selb1, ROWB));
            bfr[2 * nt2][0]     = r[0];
            bfr[2 * nt2][1]     = r[1];
            bfr[2 * nt2 + 1][0] = r[2];
            bfr[2 * nt2 + 1][1] = r[3];
        }
        uint32_t afr[2][4];
#pragma unroll
        for (int mt = 0; mt < 2; mt++)
            ldsm_x4(afr[mt], sAH + swz(rowA_base + mt * 16, ks * 2 + selb2, ROWB));
#pragma unroll
        for (int mt = 0; mt < 2; mt++)
#pragma unroll
            for (int nt = 0; nt < NT; nt++)
                mma16816(acc[mt][nt], afr[mt], bfr[nt]);
#pragma unroll
        for (int mt = 0; mt < 2; mt++)
            ldsm_x4(afr[mt], sAL + swz(rowA_base + mt * 16, ks * 2 + selb2, ROWB));
#pragma unroll
        for (int mt = 0; mt < 2; mt++)
#pragma unroll
            for (int nt = 0; nt < NT; nt++)
                mma16816(acc[mt][nt], afr[mt], bfr[nt]);
    }

    __syncthreads();
    for (int idx = t; idx < BN * NG; idx += 256) {
        int rn = idx / NG, g = idx - rn * NG;
        cpasync16(sB + swz(rn, g, ROWB), Bl + (size_t)rn * K + g * 8);
    }
    cpasync_wait();
    __syncthreads();

#pragma unroll
    for (int ks = 0; ks < KS; ks++) {
        uint32_t bfr[NT][2];
#pragma unroll
        for (int nt2 = 0; nt2 < NT / 2; nt2++) {
            uint32_t r[4];
            ldsm_x4(r, sB + swz(rowB_base + nt2 * 16, ks * 2 + selb1, ROWB));
            bfr[2 * nt2][0]     = r[0];
            bfr[2 * nt2][1]     = r[1];
            bfr[2 * nt2 + 1][0] = r[2];
            bfr[2 * nt2 + 1][1] = r[3];
        }
        uint32_t afr[2][4];
#pragma unroll
        for (int mt = 0; mt < 2; mt++)
            ldsm_x4(afr[mt], sAH + swz(rowA_base + mt * 16, ks * 2 + selb2, ROWB));
#pragma unroll
        for (int mt = 0; mt < 2; mt++)
#pragma unroll
            for (int nt = 0; nt < NT; nt++)
                mma16816(acc[mt][nt], afr[mt], bfr[nt]);
    }

    const int colb = (lane & 3) * 2;
    if (wn == 0) {
        // fp16 Wh for agg
#pragma unroll
        for (int mt = 0; mt < 2; mt++) {
            int r0 = bm + wm * 32 + mt * 16 + (lane >> 2);
            int r1 = r0 + 8;
#pragma unroll
            for (int nt = 0; nt < NT; nt++) {
                int col = colb + nt * 8;
                if (r0 < M) *(__half2*)(H16 + (size_t)r0 * 128 + col) =
                    __floats2half2_rn(acc[mt][nt][0], acc[mt][nt][1]);
                if (r1 < M) *(__half2*)(H16 + (size_t)r1 * 128 + col) =
                    __floats2half2_rn(acc[mt][nt][2], acc[mt][nt][3]);
            }
        }
        // fused el/er
#pragma unroll
        for (int mt = 0; mt < 2; mt++) {
            float e[8];
#pragma unroll
            for (int q = 0; q < 8; q++) e[q] = 0.f;
#pragma unroll
            for (int nt = 0; nt < NT; nt++) {
                int c = colb + nt * 8;
                float a0 = al[c], a1 = al[c + 1];
                float b0 = ar[c], b1 = ar[c + 1];
                float sl0 = acc[mt][nt][0] * a0 + acc[mt][nt][1] * a1;
                float sl1 = acc[mt][nt][2] * a0 + acc[mt][nt][3] * a1;
                float sr0 = acc[mt][nt][0] * b0 + acc[mt][nt][1] * b1;
                float sr1 = acc[mt][nt][2] * b0 + acc[mt][nt][3] * b1;
                int hsel = (nt < 8) ? 0 : 1;
                e[hsel]     += sl0;
                e[2 + hsel] += sr0;
                e[4 + hsel] += sl1;
                e[6 + hsel] += sr1;
            }
#pragma unroll
            for (int o = 1; o <= 2; o <<= 1)
#pragma unroll
                for (int q = 0; q < 8; q++)
                    e[q] += __shfl_xor_sync(0xffffffffu, e[q], o);
            if ((lane & 3) == 0) {
                int r0 = bm + wm * 32 + mt * 16 + (lane >> 2);
                int r1 = r0 + 8;
                if (r0 < M) {
                    el[2 * r0] = e[0]; el[2 * r0 + 1] = e[1];
                    er[2 * r0] = e[2]; er[2 * r0 + 1] = e[3];
                }
                if (r1 < M) {
                    el[2 * r1] = e[4]; el[2 * r1 + 1] = e[5];
                    er[2 * r1] = e[6]; er[2 * r1 + 1] = e[7];
                }
            }
        }
    } else {
        // fp32 residual
#pragma unroll
        for (int mt = 0; mt < 2; mt++) {
            int r0 = bm + wm * 32 + mt * 16 + (lane >> 2);
            int r1 = r0 + 8;
#pragma unroll
            for (int nt = 0; nt < NT; nt++) {
                int col = colb + nt * 8;
                if (r0 < M) *(float2*)&C2[(size_t)r0 * 128 + col] =
                    make_float2(acc[mt][nt][0], acc[mt][nt][1]);
                if (r1 < M) *(float2*)&C2[(size_t)r1 * 128 + col] =
                    make_float2(acc[mt][nt][2], acc[mt][nt][3]);
            }
        }
    }
}

// ---------------------------------------------------------------------------
// Small bf16x3 GEMM (pg layers): fp16 output + fused el/er epilogue.
// ---------------------------------------------------------------------------
template <int BN, int K>
__global__ __launch_bounds__(256, 1) void tc_gemm_small(
    const float* __restrict__ A1,
    const uint16_t* __restrict__ Bh, const uint16_t* __restrict__ Bl,
    const float* __restrict__ al, const float* __restrict__ ar,
    float* __restrict__ el, float* __restrict__ er,
    __half* __restrict__ H16, int M)
{
    constexpr int ROWB = K * 2;
    constexpr int NG   = K / 8;
    constexpr int WN   = BN / 2;
    constexpr int NT   = WN / 8;
    constexpr int KS   = K / 16;

    extern __shared__ char smem[];
    const uint32_t sAH = smem_u32(smem);
    const uint32_t sAL = sAH + 128 * ROWB;
    const uint32_t sBH = sAL + 128 * ROWB;
    const uint32_t sBL = sBH + BN * ROWB;

    const int t    = threadIdx.x;
    const int wid  = t >> 5;
    const int lane = t & 31;
    const int bm   = blockIdx.x * 128;

    for (int idx = t; idx < BN * NG; idx += 256) {
        int rn = idx / NG, g = idx - rn * NG, k0 = g * 8;
        cpasync16(sBH + swz(rn, g, ROWB), Bh + (size_t)rn * K + k0);
        cpasync16(sBL + swz(rn, g, ROWB), Bl + (size_t)rn * K + k0);
    }
    for (int idx = t; idx < 128 * NG; idx += 256) {
        int row = idx / NG, g = idx - row * NG, k0 = g * 8;
        int grow = bm + row;
        float v[8] = {0, 0, 0, 0, 0, 0, 0, 0};
        if (grow < M) {
            const float* p = A1 + (size_t)grow * K + k0;
            *(float4*)&v[0] = ((const float4*)p)[0];
            *(float4*)&v[4] = ((const float4*)p)[1];
        }
        uint4 h4, l4;
        split8(v, h4, l4);
        uint32_t o = swz(row, g, ROWB);
        *(uint4*)(smem + o) = h4;
        *(uint4*)(smem + 128 * ROWB + o) = l4;
    }
    cpasync_wait();
    __syncthreads();

    const int wm = wid & 3;
    const int wn = wid >> 2;
    const int lr   = lane & 7;
    const int sel  = lane >> 3;
    const int selb1 = sel & 1;
    const int selb2 = sel >> 1;
    const int rowA_base = wm * 32 + lr + selb1 * 8;
    const int rowB_base = wn * WN + lr + selb2 * 8;

    float acc[2][NT][4];
#pragma unroll
    for (int mt = 0; mt < 2; mt++)
#pragma unroll
        for (int nt = 0; nt < NT; nt++)
#pragma unroll
            for (int q = 0; q < 4; q++) acc[mt][nt][q] = 0.f;

#pragma unroll
    for (int pr = 0; pr < 3; pr++) {
        const uint32_t baseA = (pr == 2) ? sAL : sAH;
        const uint32_t baseB = (pr == 1) ? sBL : sBH;
#pragma unroll
        for (int ks = 0; ks < KS; ks++) {
            uint32_t afr[2][4];
#pragma unroll
            for (int mt = 0; mt < 2; mt++)
                ldsm_x4(afr[mt], baseA + swz(rowA_base + mt * 16, ks * 2 + selb2, ROWB));
            uint32_t bfr[NT][2];
#pragma unroll
            for (int nt2 = 0; nt2 < NT / 2; nt2++) {
                uint32_t r[4];
                ldsm_x4(r, baseB + swz(rowB_base + nt2 * 16, ks * 2 + selb1, ROWB));
                bfr[2 * nt2][0]     = r[0];
                bfr[2 * nt2][1]     = r[1];
                bfr[2 * nt2 + 1][0] = r[2];
                bfr[2 * nt2 + 1][1] = r[3];
            }
#pragma unroll
            for (int mt = 0; mt < 2; mt++)
#pragma unroll
                for (int nt = 0; nt < NT; nt++)
                    mma16816(acc[mt][nt], afr[mt], bfr[nt]);
        }
    }

    const int colb = wn * WN + (lane & 3) * 2;
#pragma unroll
    for (int mt = 0; mt < 2; mt++) {
        int r0 = bm + wm * 32 + mt * 16 + (lane >> 2);
        int r1 = r0 + 8;
#pragma unroll
        for (int nt = 0; nt < NT; nt++) {
            int col = colb + nt * 8;
            if (r0 < M) *(__half2*)(H16 + (size_t)r0 * BN + col) =
                __floats2half2_rn(acc[mt][nt][0], acc[mt][nt][1]);
            if (r1 < M) *(__half2*)(H16 + (size_t)r1 * BN + col) =
                __floats2half2_rn(acc[mt][nt][2], acc[mt][nt][3]);
        }
    }

#pragma unroll
    for (int mt = 0; mt < 2; mt++) {
        float e[4];
#pragma unroll
        for (int q = 0; q < 4; q++) e[q] = 0.f;
#pragma unroll
        for (int nt = 0; nt < NT; nt++) {
            int c = colb + nt * 8;
            float a0 = al[c], a1 = al[c + 1];
            float b0 = ar[c], b1 = ar[c + 1];
            e[0] += acc[mt][nt][0] * a0 + acc[mt][nt][1] * a1;
            e[1] += acc[mt][nt][0] * b0 + acc[mt][nt][1] * b1;
            e[2] += acc[mt][nt][2] * a0 + acc[mt][nt][3] * a1;
            e[3] += acc[mt][nt][2] * b0 + acc[mt][nt][3] * b1;
        }
#pragma unroll
        for (int o = 1; o <= 2; o <<= 1)
#pragma unroll
            for (int q = 0; q < 4; q++)
                e[q] += __shfl_xor_sync(0xffffffffu, e[q], o);
        if ((lane & 3) == 0) {
            int r0 = bm + wm * 32 + mt * 16 + (lane >> 2);
            int r1 = r0 + 8;
            if (r0 < M) { el[2 * r0 + wn] = e[0]; er[2 * r0 + wn] = e[1]; }
            if (r1 < M) { el[2 * r1 + wn] = e[2]; er[2 * r1 + wn] = e[3]; }
        }
    }
}

// ---------------------------------------------------------------------------
// CSR build
// ---------------------------------------------------------------------------
__global__ void count_kernel(const int* __restrict__ dst, int e) {
    int i = blockIdx.x * blockDim.x + threadIdx.x;
    if (i < e) atomicAdd(&g_cnt[dst[i]], 1);
}

__global__ void scan_kernel(int n) {
    __shared__ int partial[1024];
    const int t = threadIdx.x;
    const int C = (n + 1023) / 1024;
    int s = 0;
    for (int j = 0; j < C; j++) {
        int idx = t * C + j;
        if (idx < n) s += g_cnt[idx];
    }
    partial[t] = s;
    __syncthreads();
    for (int ofs = 1; ofs < 1024; ofs <<= 1) {
        int v = (t >= ofs) ? partial[t - ofs] : 0;
        __syncthreads();
        partial[t] += v;
        __syncthreads();
    }
    int run = (t == 0) ? 0 : partial[t - 1];
    for (int j = 0; j < C; j++) {
        int idx = t * C + j;
        if (idx < n) {
            g_off[idx] = run;
            run += g_cnt[idx];
            g_cnt[idx] = 0;
        }
    }
    if (t == 1023) g_off[n] = run;
}

__global__ void fill_kernel(const int* __restrict__ src, const int* __restrict__ dst, int e) {
    int i = blockIdx.x * blockDim.x + threadIdx.x;
    if (i < e) {
        int d = dst[i];
        int p = atomicAdd(&g_cnt[d], 1);
        g_esrc[g_off[d] + p] = src[i];
    }
}

// ---------------------------------------------------------------------------
// Aggregation: warp per dst node, single-pass online softmax, fp16 h gather.
// ---------------------------------------------------------------------------
__device__ __forceinline__ float leaky02(float x) { return x > 0.f ? x : 0.2f * x; }

template <int HD>
__device__ __forceinline__ void load_h16(float* hv, const __half* h, int s, int lane) {
    constexpr int V = HD / 32;
    if (V == 4) {
        uint2 raw = *(const uint2*)(h + (size_t)s * HD + lane * 4);
        float2 fa = __half22float2(*(__half2*)&raw.x);
        float2 fb = __half22float2(*(__half2*)&raw.y);
        hv[0] = fa.x; hv[1] = fa.y; hv[2] = fb.x; hv[3] = fb.y;
    } else {
        uint32_t raw = *(const uint32_t*)(h + (size_t)s * HD + lane * 2);
        float2 fa = __half22float2(*(__half2*)&raw);
        hv[0] = fa.x; hv[1] = fa.y;
    }
}

template <int HD, int ACT, bool HEADMEAN>
__global__ void agg_kernel(const __half* __restrict__ h,
                           const float* __restrict__ res,
                           const float* __restrict__ elp,
                           const float* __restrict__ erp,
                           float* __restrict__ out, int n)
{
    constexpr int V = HD / 32;
    int node = (blockIdx.x * blockDim.x + threadIdx.x) >> 5;
    int lane = threadIdx.x & 31;
    if (node >= n) return;

    const int beg = g_off[node];
    const int end = g_off[node + 1];
    const float2 erv = ((const float2*)erp)[node];
    const float2* __restrict__ el2 = (const float2*)elp;
    const int* __restrict__ esrc = g_esrc;

    const bool head0 = (lane * V) < (HD / 2);
    float m0 = -1e30f, m1 = -1e30f;
    float d0 = 0.f, d1 = 0.f;
    float acc[V];
#pragma unroll
    for (int q = 0; q < V; q++) acc[q] = 0.f;

    int i = beg;
    for (; i + 4 <= end; i += 4) {
        int s[4];
#pragma unroll
        for (int j = 0; j < 4; j++) s[j] = esrc[i + j];
        float2 ev[4];
#pragma unroll
        for (int j = 0; j < 4; j++) ev[j] = el2[s[j]];
        float hv[4][V];
#pragma unroll
        for (int j = 0; j < 4; j++) load_h16<HD>(hv[j], h, s[j], lane);
#pragma unroll
        for (int j = 0; j < 4; j++) {
            float e0 = leaky02(ev[j].x + erv.x);
            float e1 = leaky02(ev[j].y + erv.y);
            float nm0 = fmaxf(m0, e0), nm1 = fmaxf(m1, e1);
            float sc0 = __expf(m0 - nm0), w0 = __expf(e0 - nm0);
            float sc1 = __expf(m1 - nm1), w1 = __expf(e1 - nm1);
            d0 = d0 * sc0 + w0;
            d1 = d1 * sc1 + w1;
            m0 = nm0; m1 = nm1;
            float scv = head0 ? sc0 : sc1;
            float wv  = head0 ? w0  : w1;
#pragma unroll
            for (int q = 0; q < V; q++) acc[q] = fmaf(acc[q], scv, wv * hv[j][q]);
        }
    }
    for (; i < end; i++) {
        int s = esrc[i];
        float2 ev = el2[s];
        float hv[V];
        load_h16<HD>(hv, h, s, lane);
        float e0 = leaky02(ev.x + erv.x);
        float e1 = leaky02(ev.y + erv.y);
        float nm0 = fmaxf(m0, e0), nm1 = fmaxf(m1, e1);
        float sc0 = __expf(m0 - nm0), w0 = __expf(e0 - nm0);
        float sc1 = __expf(m1 - nm1), w1 = __expf(e1 - nm1);
        d0 = d0 * sc0 + w0;
        d1 = d1 * sc1 + w1;
        m0 = nm0; m1 = nm1;
        float scv = head0 ? sc0 : sc1;
        float wv  = head0 ? w0  : w1;
#pragma unroll
        for (int q = 0; q < V; q++) acc[q] = fmaf(acc[q], scv, wv * hv[q]);
    }

    const bool has = (end > beg);
    const float inv0 = has ? 1.f / d0 : 0.f;
    const float inv1 = has ? 1.f / d1 : 0.f;
    const float invv = head0 ? inv0 : inv1;

    float rr[V];
    if (V == 4) *(float4*)rr = *(const float4*)(res + (size_t)node * HD + lane * V);
    else        *(float2*)rr = *(const float2*)(res + (size_t)node * HD + lane * V);

    float v[V];
#pragma unroll
    for (int q = 0; q < V; q++) {
        v[q] = acc[q] * invv + rr[q];
        if (ACT == 0) v[q] = v[q] > 0.f ? v[q] : expm1f(v[q]);
        else          v[q] = tanhf(v[q]);
    }

    if (HEADMEAN) {
        float p[V];
#pragma unroll
        for (int q = 0; q < V; q++) p[q] = __shfl_xor_sync(0xffffffffu, v[q], 16);
        if (lane < 16) {
            float o[V];
#pragma unroll
            for (int q = 0; q < V; q++) o[q] = 0.5f * (v[q] + p[q]);
            if (V == 4) *(float4*)(out + (size_t)node * 64 + lane * V) = *(float4*)o;
            else        *(float2*)(out + (size_t)node * 64 + lane * V) = *(float2*)o;
        }
    } else {
        if (V == 4) *(float4*)(out + (size_t)node * HD + lane * V) = *(float4*)v;
        else        *(float2*)(out + (size_t)node * HD + lane * V) = *(float2*)v;
    }
}

// ---------------------------------------------------------------------------
// Launch — multi-stream graph (s1 = gat, s2 = pg, s0 = CSR).
// ---------------------------------------------------------------------------
extern "C" void kernel_launch(void* const* d_in, const int* in_sizes, int n_in,
                              void* d_out, int out_size)
{
    const float* fvs = (const float*)d_in[0];
    const float* pos = (const float*)d_in[1];
    const int*   src = (const int*)d_in[2];
    const int*   dst = (const int*)d_in[3];
    const float* g0W  = (const float*)d_in[4];
    const float* g0al = (const float*)d_in[5];
    const float* g0ar = (const float*)d_in[6];
    const float* g0rW = (const float*)d_in[7];
    const float* g1W  = (const float*)d_in[8];
    const float* g1al = (const float*)d_in[9];
    const float* g1ar = (const float*)d_in[10];
    const float* g1rW = (const float*)d_in[11];
    const float* g2W  = (const float*)d_in[12];
    const float* g2al = (const float*)d_in[13];
    const float* g2ar = (const float*)d_in[14];
    const float* g2rW = (const float*)d_in[15];
    const float* p0W  = (const float*)d_in[16];
    const float* p0al = (const float*)d_in[17];
    const float* p0ar = (const float*)d_in[18];
    const float* p1W  = (const float*)d_in[19];
    const float* p1al = (const float*)d_in[20];
    const float* p1ar = (const float*)d_in[21];

    const int n = in_sizes[0] / 128;
    const int e = in_sizes[2];

    float *rh, *hs, *hs2, *hp, *el, *er, *el2, *er2;
    __half *h16, *hq16;
    int* cnt;
    uint16_t *wthi, *wtlo;
    cudaGetSymbolAddress((void**)&h16,  g_h16);
    cudaGetSymbolAddress((void**)&hq16, g_hq16);
    cudaGetSymbolAddress((void**)&rh,   g_rh);
    cudaGetSymbolAddress((void**)&hs,   g_hs);
    cudaGetSymbolAddress((void**)&hs2,  g_hs2);
    cudaGetSymbolAddress((void**)&hp,   g_hp);
    cudaGetSymbolAddress((void**)&el,   g_el);
    cudaGetSymbolAddress((void**)&er,   g_er);
    cudaGetSymbolAddress((void**)&el2,  g_el2);
    cudaGetSymbolAddress((void**)&er2,  g_er2);
    cudaGetSymbolAddress((void**)&cnt,  g_cnt);
    cudaGetSymbolAddress((void**)&wthi, g_wthi);
    cudaGetSymbolAddress((void**)&wtlo, g_wtlo);

    float* out_hs = (float*)d_out;
    float* out_hp = (float*)d_out + (size_t)n * 64;

    const int EB = (e + 255) / 256;
    const int GB = (n + 127) / 128;
    const int WB = (n + 7) / 8;

    constexpr int SMEM_F     = 2 * 128 * 384 + 256 * 384;          // 196608
    constexpr int SMEM_SMALL = (128 + 128 + 64 + 64) * 64 * 2;     // 49152
    cudaFuncSetAttribute(tc_gemm_fused<192>,    cudaFuncAttributeMaxDynamicSharedMemorySize, SMEM_F);
    cudaFuncSetAttribute(tc_gemm_small<64, 64>, cudaFuncAttributeMaxDynamicSharedMemorySize, SMEM_SMALL);

    static cudaStream_t s1 = nullptr, s2 = nullptr;
    static cudaEvent_t evFork, evPrep, evCSR, evP0, evP1, evEnd1, evEnd2;
    if (s1 == nullptr) {
        cudaStreamCreateWithFlags(&s1, cudaStreamNonBlocking);
        cudaStreamCreateWithFlags(&s2, cudaStreamNonBlocking);
        cudaEventCreateWithFlags(&evFork, cudaEventDisableTiming);
        cudaEventCreateWithFlags(&evPrep, cudaEventDisableTiming);
        cudaEventCreateWithFlags(&evCSR,  cudaEventDisableTiming);
        cudaEventCreateWithFlags(&evP0,   cudaEventDisableTiming);
        cudaEventCreateWithFlags(&evP1,   cudaEventDisableTiming);
        cudaEventCreateWithFlags(&evEnd1, cudaEventDisableTiming);
        cudaEventCreateWithFlags(&evEnd2, cudaEventDisableTiming);
    }

    Prep8 pa;
    const float* Ws[8] = {g0W, g0rW, g1W, g1rW, g2W, g2rW, p0W, p1W};
    for (int m = 0; m < 8; m++) {
        pa.W[m] = Ws[m];
        pa.K[m] = (m < 6) ? 192 : 64;
        pa.N[m] = (m < 6) ? 128 : 64;
        pa.off[m] = (m < 6) ? (m >> 1) * WT_FUSED + (m & 1) * (128 * 192)
                            : 3 * WT_FUSED + (m - 6) * WT_SMALL;
    }

    const int F0 = 0 * WT_FUSED, F1 = 1 * WT_FUSED, F2 = 2 * WT_FUSED;
    const int P0 = 3 * WT_FUSED, P1 = 3 * WT_FUSED + WT_SMALL;

    // ---- fork ----
    cudaEventRecord(evFork, 0);
    cudaStreamWaitEvent(s1, evFork, 0);
    cudaStreamWaitEvent(s2, evFork, 0);

    prep_kernel<<<64, 256, 0, s1>>>(pa);
    cudaEventRecord(evPrep, s1);
    cudaStreamWaitEvent(s2, evPrep, 0);

    // s0: CSR build — concurrent with prep + first GEMMs
    cudaMemsetAsync(cnt, 0, (size_t)n * sizeof(int), 0);
    count_kernel<<<EB, 256, 0, 0>>>(dst, e);
    scan_kernel<<<1, 1024, 0, 0>>>(n);
    fill_kernel<<<EB, 256, 0, 0>>>(src, dst, e);
    cudaEventRecord(evCSR, 0);

    // ---- layer 0 ----
    tc_gemm_fused<192><<<GB, 256, SMEM_F, s1>>>(fvs, 128, pos, wthi + F0, wtlo + F0,
                                                g0al, g0ar, el, er, h16, rh, n);
    tc_gemm_small<64, 64><<<GB, 256, SMEM_SMALL, s2>>>(pos, wthi + P0, wtlo + P0,
                                                       p0al, p0ar, el2, er2, hq16, n);
    cudaStreamWaitEvent(s1, evCSR, 0);
    cudaStreamWaitEvent(s2, evCSR, 0);
    agg_kernel<128, 0, false><<<WB, 256, 0, s1>>>(h16, rh, el, er, hs, n);
    agg_kernel<64, 1, false><<<WB, 256, 0, s2>>>(hq16, pos, el2, er2, hp, n);
    cudaEventRecord(evP0, s2);

    // ---- layer 1 ----
    cudaStreamWaitEvent(s1, evP0, 0);
    tc_gemm_fused<192><<<GB, 256, SMEM_F, s1>>>(hs, 128, hp, wthi + F1, wtlo + F1,
                                                g1al, g1ar, el, er, h16, rh, n);
    agg_kernel<128, 0, false><<<WB, 256, 0, s1>>>(h16, rh, el, er, hs2, n);

    tc_gemm_small<64, 64><<<GB, 256, SMEM_SMALL, s2>>>(hp, wthi + P1, wtlo + P1,
                                                       p1al, p1ar, el2, er2, hq16, n);
    agg_kernel<64, 1, false><<<WB, 256, 0, s2>>>(hq16, hp, el2, er2, out_hp, n);
    cudaEventRecord(evP1, s2);

    // ---- layer 2 (output, head-mean) ----
    cudaStreamWaitEvent(s1, evP1, 0);
    tc_gemm_fused<192><<<GB, 256, SMEM_F, s1>>>(hs2, 128, out_hp, wthi + F2, wtlo + F2,
                                                g2al, g2ar, el, er, h16, rh, n);
    agg_kernel<128, 0, true><<<WB, 256, 0, s1>>>(h16, rh, el, er, out_hs, n);
    cudaEventRecord(evEnd1, s1);
    cudaEventRecord(evEnd2, s2);

    // ---- join ----
    cudaStreamWaitEvent(0, evEnd1, 0);
    cudaStreamWaitEvent(0, evEnd2, 0);
}

// round 13
// speedup vs baseline: 1.4071x; 1.4071x over previous
#include <cuda_runtime.h>
#include <cuda_bf16.h>
#include <math.h>
#include <stdint.h>

// ---------------------------------------------------------------------------
// Problem constants
// ---------------------------------------------------------------------------
#define NMAX 50000
#define EMAX 800000

// ---------------------------------------------------------------------------
// Scratch (device globals) — gat-chain h/rh/el/er are double-buffered so the
// next layer's GEMM can run concurrently with the tail of this layer's agg.
// ---------------------------------------------------------------------------
__device__ float g_h  [2][(size_t)NMAX * 128];
__device__ float g_rh [2][(size_t)NMAX * 128];
__device__ float g_el [2][(size_t)NMAX * 2];
__device__ float g_er [2][(size_t)NMAX * 2];
__device__ float g_hs [(size_t)NMAX * 128];
__device__ float g_hs2[(size_t)NMAX * 128];
__device__ float g_hp [(size_t)NMAX * 64];
__device__ float g_hq [(size_t)NMAX * 64];
__device__ float g_el2[(size_t)NMAX * 2];
__device__ float g_er2[(size_t)NMAX * 2];
__device__ int   g_off[NMAX + 1];
__device__ int   g_cnt[NMAX];
__device__ int   g_esrc[EMAX];

#define WT_FUSED (256 * 192)
#define WT_SMALL (64 * 64)
__device__ uint16_t g_wthi[3 * WT_FUSED + 2 * WT_SMALL];
__device__ uint16_t g_wtlo[3 * WT_FUSED + 2 * WT_SMALL];

// ---------------------------------------------------------------------------
// Helpers
// ---------------------------------------------------------------------------
__device__ __forceinline__ uint32_t smem_u32(const void* p) {
    uint32_t a;
    asm("{ .reg .u64 t; cvta.to.shared.u64 t, %1; cvt.u32.u64 %0, t; }"
        : "=r"(a) : "l"(p));
    return a;
}

__device__ __forceinline__ void ldsm_x4(uint32_t* r, uint32_t addr) {
    asm volatile("ldmatrix.sync.aligned.m8n8.x4.shared.b16 {%0,%1,%2,%3}, [%4];"
                 : "=r"(r[0]), "=r"(r[1]), "=r"(r[2]), "=r"(r[3]) : "r"(addr));
}

__device__ __forceinline__ void mma16816(float* c, const uint32_t* a, const uint32_t* b) {
    asm volatile(
        "mma.sync.aligned.m16n8k16.row.col.f32.bf16.bf16.f32 "
        "{%0,%1,%2,%3}, {%4,%5,%6,%7}, {%8,%9}, {%0,%1,%2,%3};"
        : "+f"(c[0]), "+f"(c[1]), "+f"(c[2]), "+f"(c[3])
        : "r"(a[0]), "r"(a[1]), "r"(a[2]), "r"(a[3]), "r"(b[0]), "r"(b[1]));
}

__device__ __forceinline__ void cpasync16(uint32_t s, const void* g) {
    asm volatile("cp.async.cg.shared.global [%0], [%1], 16;" :: "r"(s), "l"(g));
}
__device__ __forceinline__ void cpasync_wait() {
    asm volatile("cp.async.commit_group;");
    asm volatile("cp.async.wait_group 0;" ::: "memory");
}

__device__ __forceinline__ void split8(const float* v, uint4& h4, uint4& l4) {
    uint16_t* hp = (uint16_t*)&h4;
    uint16_t* lp = (uint16_t*)&l4;
#pragma unroll
    for (int i = 0; i < 8; i++) {
        __nv_bfloat16 hb = __float2bfloat16(v[i]);
        float r = v[i] - __bfloat162float(hb);
        __nv_bfloat16 lb = __float2bfloat16(r);
        hp[i] = *(uint16_t*)&hb;
        lp[i] = *(uint16_t*)&lb;
    }
}

__device__ __forceinline__ uint32_t swz(int row, int g, int ROWB) {
    int c = (g & ~7) | ((g ^ row) & 7);
    return (uint32_t)(row * ROWB + c * 16);
}

// ---------------------------------------------------------------------------
// Weight prep
// ---------------------------------------------------------------------------
struct Prep8 {
    const float* W[8];
    int K[8], N[8], off[8];
};

__global__ void prep_kernel(Prep8 p) {
    for (int m = 0; m < 8; m++) {
        const int K = p.K[m], N = p.N[m], tot = K * N, off = p.off[m];
        const float* W = p.W[m];
        for (int idx = blockIdx.x * blockDim.x + threadIdx.x; idx < tot;
             idx += gridDim.x * blockDim.x) {
            int n = idx / K, k = idx - n * K;
            float w = W[(size_t)k * N + n];
            __nv_bfloat16 h = __float2bfloat16(w);
            float r = w - __bfloat162float(h);
            __nv_bfloat16 l = __float2bfloat16(r);
            g_wthi[off + idx] = *(uint16_t*)&h;
            g_wtlo[off + idx] = *(uint16_t*)&l;
        }
    }
}

// ---------------------------------------------------------------------------
// Fused bf16x3 GEMM + el/er epilogue (gat chain). row0 = M-tile base offset.
// ---------------------------------------------------------------------------
template <int K>
__global__ __launch_bounds__(256, 1) void tc_gemm_fused(
    const float* __restrict__ A1, int K1,
    const float* __restrict__ A2,
    const uint16_t* __restrict__ Bh, const uint16_t* __restrict__ Bl,
    const float* __restrict__ al, const float* __restrict__ ar,
    float* __restrict__ el, float* __restrict__ er,
    float* __restrict__ C1, float* __restrict__ C2, int M, int row0)
{
    constexpr int BN   = 256;
    constexpr int ROWB = K * 2;
    constexpr int NG   = K / 8;
    constexpr int WN   = 128;
    constexpr int NT   = WN / 8;
    constexpr int KS   = K / 16;
    constexpr int AOFF  = 0;
    constexpr int ALOFF = 128 * ROWB;
    constexpr int BOFF  = 2 * 128 * ROWB;

    extern __shared__ char smem[];
    const uint32_t sb  = smem_u32(smem);
    const uint32_t sAH = sb + AOFF;
    const uint32_t sAL = sb + ALOFF;
    const uint32_t sB  = sb + BOFF;

    const int t    = threadIdx.x;
    const int wid  = t >> 5;
    const int lane = t & 31;
    const int bm   = row0 + blockIdx.x * 128;

    for (int idx = t; idx < BN * NG; idx += 256) {
        int rn = idx / NG, g = idx - rn * NG;
        cpasync16(sB + swz(rn, g, ROWB), Bh + (size_t)rn * K + g * 8);
    }

    for (int idx = t; idx < 128 * NG; idx += 256) {
        int row = idx / NG, g = idx - row * NG, k0 = g * 8;
        int grow = bm + row;
        float v[8] = {0, 0, 0, 0, 0, 0, 0, 0};
        if (grow < M) {
            const float* p = (k0 < K1) ? (A1 + (size_t)grow * K1 + k0)
                                       : (A2 + (size_t)grow * (K - K1) + (k0 - K1));
            *(float4*)&v[0] = ((const float4*)p)[0];
            *(float4*)&v[4] = ((const float4*)p)[1];
        }
        uint4 h4, l4;
        split8(v, h4, l4);
        uint32_t o = swz(row, g, ROWB);
        *(uint4*)(smem + AOFF + o)  = h4;
        *(uint4*)(smem + ALOFF + o) = l4;
    }
    cpasync_wait();
    __syncthreads();

    const int wm   = wid & 3;
    const int wn   = wid >> 2;
    const int lr   = lane & 7;
    const int sel  = lane >> 3;
    const int selb1 = sel & 1;
    const int selb2 = sel >> 1;
    const int rowA_base = wm * 32 + lr + selb1 * 8;
    const int rowB_base = wn * WN + lr + selb2 * 8;

    float acc[2][NT][4];
#pragma unroll
    for (int mt = 0; mt < 2; mt++)
#pragma unroll
        for (int nt = 0; nt < NT; nt++)
#pragma unroll
            for (int q = 0; q < 4; q++) acc[mt][nt][q] = 0.f;

#pragma unroll
    for (int ks = 0; ks < KS; ks++) {
        uint32_t bfr[NT][2];
#pragma unroll
        for (int nt2 = 0; nt2 < NT / 2; nt2++) {
            uint32_t r[4];
            ldsm_x4(r, sB + swz(rowB_base + nt2 * 16, ks * 2 + selb1, ROWB));
            bfr[2 * nt2][0]     = r[0];
            bfr[2 * nt2][1]     = r[1];
            bfr[2 * nt2 + 1][0] = r[2];
            bfr[2 * nt2 + 1][1] = r[3];
        }
        uint32_t afr[2][4];
#pragma unroll
        for (int mt = 0; mt < 2; mt++)
            ldsm_x4(afr[mt], sAH + swz(rowA_base + mt * 16, ks * 2 + selb2, ROWB));
#pragma unroll
        for (int mt = 0; mt < 2; mt++)
#pragma unroll
            for (int nt = 0; nt < NT; nt++)
                mma16816(acc[mt][nt], afr[mt], bfr[nt]);
#pragma unroll
        for (int mt = 0; mt < 2; mt++)
            ldsm_x4(afr[mt], sAL + swz(rowA_base + mt * 16, ks * 2 + selb2, ROWB));
#pragma unroll
        for (int mt = 0; mt < 2; mt++)
#pragma unroll
            for (int nt = 0; nt < NT; nt++)
                mma16816(acc[mt][nt], afr[mt], bfr[nt]);
    }

    __syncthreads();
    for (int idx = t; idx < BN * NG; idx += 256) {
        int rn = idx / NG, g = idx - rn * NG;
        cpasync16(sB + swz(rn, g, ROWB), Bl + (size_t)rn * K + g * 8);
    }
    cpasync_wait();
    __syncthreads();

#pragma unroll
    for (int ks = 0; ks < KS; ks++) {
        uint32_t bfr[NT][2];
#pragma unroll
        for (int nt2 = 0; nt2 < NT / 2; nt2++) {
            uint32_t r[4];
            ldsm_x4(r, sB + swz(rowB_base + nt2 * 16, ks * 2 + selb1, ROWB));
            bfr[2 * nt2][0]     = r[0];
            bfr[2 * nt2][1]     = r[1];
            bfr[2 * nt2 + 1][0] = r[2];
            bfr[2 * nt2 + 1][1] = r[3];
        }
        uint32_t afr[2][4];
#pragma unroll
        for (int mt = 0; mt < 2; mt++)
            ldsm_x4(afr[mt], sAH + swz(rowA_base + mt * 16, ks * 2 + selb2, ROWB));
#pragma unroll
        for (int mt = 0; mt < 2; mt++)
#pragma unroll
            for (int nt = 0; nt < NT; nt++)
                mma16816(acc[mt][nt], afr[mt], bfr[nt]);
    }

    float* __restrict__ C = (wn == 0) ? C1 : C2;
    const int colb = (lane & 3) * 2;
#pragma unroll
    for (int mt = 0; mt < 2; mt++) {
        int r0 = bm + wm * 32 + mt * 16 + (lane >> 2);
        int r1 = r0 + 8;
#pragma unroll
        for (int nt = 0; nt < NT; nt++) {
            int col = colb + nt * 8;
            if (r0 < M) *(float2*)&C[(size_t)r0 * 128 + col] =
                make_float2(acc[mt][nt][0], acc[mt][nt][1]);
            if (r1 < M) *(float2*)&C[(size_t)r1 * 128 + col] =
                make_float2(acc[mt][nt][2], acc[mt][nt][3]);
        }
    }

    if (wn == 0) {
#pragma unroll
        for (int mt = 0; mt < 2; mt++) {
            float e[8];
#pragma unroll
            for (int q = 0; q < 8; q++) e[q] = 0.f;
#pragma unroll
            for (int nt = 0; nt < NT; nt++) {
                int c = colb + nt * 8;
                float a0 = al[c], a1 = al[c + 1];
                float b0 = ar[c], b1 = ar[c + 1];
                float sl0 = acc[mt][nt][0] * a0 + acc[mt][nt][1] * a1;
                float sl1 = acc[mt][nt][2] * a0 + acc[mt][nt][3] * a1;
                float sr0 = acc[mt][nt][0] * b0 + acc[mt][nt][1] * b1;
                float sr1 = acc[mt][nt][2] * b0 + acc[mt][nt][3] * b1;
                int hsel = (nt < 8) ? 0 : 1;
                e[hsel]     += sl0;
                e[2 + hsel] += sr0;
                e[4 + hsel] += sl1;
                e[6 + hsel] += sr1;
            }
#pragma unroll
            for (int o = 1; o <= 2; o <<= 1)
#pragma unroll
                for (int q = 0; q < 8; q++)
                    e[q] += __shfl_xor_sync(0xffffffffu, e[q], o);
            if ((lane & 3) == 0) {
                int r0 = bm + wm * 32 + mt * 16 + (lane >> 2);
                int r1 = r0 + 8;
                if (r0 < M) {
                    el[2 * r0] = e[0]; el[2 * r0 + 1] = e[1];
                    er[2 * r0] = e[2]; er[2 * r0 + 1] = e[3];
                }
                if (r1 < M) {
                    el[2 * r1] = e[4]; el[2 * r1 + 1] = e[5];
                    er[2 * r1] = e[6]; er[2 * r1 + 1] = e[7];
                }
            }
        }
    }
}

// ---------------------------------------------------------------------------
// Small bf16x3 GEMM (pg layers) with fused el/er epilogue
// ---------------------------------------------------------------------------
template <int BN, int K>
__global__ __launch_bounds__(256, 1) void tc_gemm_small(
    const float* __restrict__ A1,
    const uint16_t* __restrict__ Bh, const uint16_t* __restrict__ Bl,
    const float* __restrict__ al, const float* __restrict__ ar,
    float* __restrict__ el, float* __restrict__ er,
    float* __restrict__ C, int M)
{
    constexpr int ROWB = K * 2;
    constexpr int NG   = K / 8;
    constexpr int WN   = BN / 2;
    constexpr int NT   = WN / 8;
    constexpr int KS   = K / 16;

    extern __shared__ char smem[];
    const uint32_t sAH = smem_u32(smem);
    const uint32_t sAL = sAH + 128 * ROWB;
    const uint32_t sBH = sAL + 128 * ROWB;
    const uint32_t sBL = sBH + BN * ROWB;

    const int t    = threadIdx.x;
    const int wid  = t >> 5;
    const int lane = t & 31;
    const int bm   = blockIdx.x * 128;

    for (int idx = t; idx < BN * NG; idx += 256) {
        int rn = idx / NG, g = idx - rn * NG, k0 = g * 8;
        cpasync16(sBH + swz(rn, g, ROWB), Bh + (size_t)rn * K + k0);
        cpasync16(sBL + swz(rn, g, ROWB), Bl + (size_t)rn * K + k0);
    }
    for (int idx = t; idx < 128 * NG; idx += 256) {
        int row = idx / NG, g = idx - row * NG, k0 = g * 8;
        int grow = bm + row;
        float v[8] = {0, 0, 0, 0, 0, 0, 0, 0};
        if (grow < M) {
            const float* p = A1 + (size_t)grow * K + k0;
            *(float4*)&v[0] = ((const float4*)p)[0];
            *(float4*)&v[4] = ((const float4*)p)[1];
        }
        uint4 h4, l4;
        split8(v, h4, l4);
        uint32_t o = swz(row, g, ROWB);
        *(uint4*)(smem + o) = h4;
        *(uint4*)(smem + 128 * ROWB + o) = l4;
    }
    cpasync_wait();
    __syncthreads();

    const int wm = wid & 3;
    const int wn = wid >> 2;
    const int lr   = lane & 7;
    const int sel  = lane >> 3;
    const int selb1 = sel & 1;
    const int selb2 = sel >> 1;
    const int rowA_base = wm * 32 + lr + selb1 * 8;
    const int rowB_base = wn * WN + lr + selb2 * 8;

    float acc[2][NT][4];
#pragma unroll
    for (int mt = 0; mt < 2; mt++)
#pragma unroll
        for (int nt = 0; nt < NT; nt++)
#pragma unroll
            for (int q = 0; q < 4; q++) acc[mt][nt][q] = 0.f;

#pragma unroll
    for (int pr = 0; pr < 3; pr++) {
        const uint32_t baseA = (pr == 2) ? sAL : sAH;
        const uint32_t baseB = (pr == 1) ? sBL : sBH;
#pragma unroll
        for (int ks = 0; ks < KS; ks++) {
            uint32_t afr[2][4];
#pragma unroll
            for (int mt = 0; mt < 2; mt++)
                ldsm_x4(afr[mt], baseA + swz(rowA_base + mt * 16, ks * 2 + selb2, ROWB));
            uint32_t bfr[NT][2];
#pragma unroll
            for (int nt2 = 0; nt2 < NT / 2; nt2++) {
                uint32_t r[4];
                ldsm_x4(r, baseB + swz(rowB_base + nt2 * 16, ks * 2 + selb1, ROWB));
                bfr[2 * nt2][0]     = r[0];
                bfr[2 * nt2][1]     = r[1];
                bfr[2 * nt2 + 1][0] = r[2];
                bfr[2 * nt2 + 1][1] = r[3];
            }
#pragma unroll
            for (int mt = 0; mt < 2; mt++)
#pragma unroll
                for (int nt = 0; nt < NT; nt++)
                    mma16816(acc[mt][nt], afr[mt], bfr[nt]);
        }
    }

    const int colb = wn * WN + (lane & 3) * 2;
#pragma unroll
    for (int mt = 0; mt < 2; mt++) {
        int r0 = bm + wm * 32 + mt * 16 + (lane >> 2);
        int r1 = r0 + 8;
#pragma unroll
        for (int nt = 0; nt < NT; nt++) {
            int col = colb + nt * 8;
            if (r0 < M) *(float2*)&C[(size_t)r0 * BN + col] =
                make_float2(acc[mt][nt][0], acc[mt][nt][1]);
            if (r1 < M) *(float2*)&C[(size_t)r1 * BN + col] =
                make_float2(acc[mt][nt][2], acc[mt][nt][3]);
        }
    }

#pragma unroll
    for (int mt = 0; mt < 2; mt++) {
        float e[4];
#pragma unroll
        for (int q = 0; q < 4; q++) e[q] = 0.f;
#pragma unroll
        for (int nt = 0; nt < NT; nt++) {
            int c = colb + nt * 8;
            float a0 = al[c], a1 = al[c + 1];
            float b0 = ar[c], b1 = ar[c + 1];
            e[0] += acc[mt][nt][0] * a0 + acc[mt][nt][1] * a1;
            e[1] += acc[mt][nt][0] * b0 + acc[mt][nt][1] * b1;
            e[2] += acc[mt][nt][2] * a0 + acc[mt][nt][3] * a1;
            e[3] += acc[mt][nt][2] * b0 + acc[mt][nt][3] * b1;
        }
#pragma unroll
        for (int o = 1; o <= 2; o <<= 1)
#pragma unroll
            for (int q = 0; q < 4; q++)
                e[q] += __shfl_xor_sync(0xffffffffu, e[q], o);
        if ((lane & 3) == 0) {
            int r0 = bm + wm * 32 + mt * 16 + (lane >> 2);
            int r1 = r0 + 8;
            if (r0 < M) { el[2 * r0 + wn] = e[0]; er[2 * r0 + wn] = e[1]; }
            if (r1 < M) { el[2 * r1 + wn] = e[2]; er[2 * r1 + wn] = e[3]; }
        }
    }
}

// ---------------------------------------------------------------------------
// CSR build
// ---------------------------------------------------------------------------
__global__ void count_kernel(const int* __restrict__ dst, int e) {
    int i = blockIdx.x * blockDim.x + threadIdx.x;
    if (i < e) atomicAdd(&g_cnt[dst[i]], 1);
}

__global__ void scan_kernel(int n) {
    __shared__ int partial[1024];
    const int t = threadIdx.x;
    const int C = (n + 1023) / 1024;
    int s = 0;
    for (int j = 0; j < C; j++) {
        int idx = t * C + j;
        if (idx < n) s += g_cnt[idx];
    }
    partial[t] = s;
    __syncthreads();
    for (int ofs = 1; ofs < 1024; ofs <<= 1) {
        int v = (t >= ofs) ? partial[t - ofs] : 0;
        __syncthreads();
        partial[t] += v;
        __syncthreads();
    }
    int run = (t == 0) ? 0 : partial[t - 1];
    for (int j = 0; j < C; j++) {
        int idx = t * C + j;
        if (idx < n) {
            g_off[idx] = run;
            run += g_cnt[idx];
            g_cnt[idx] = 0;
        }
    }
    if (t == 1023) g_off[n] = run;
}

__global__ void fill_kernel(const int* __restrict__ src, const int* __restrict__ dst, int e) {
    int i = blockIdx.x * blockDim.x + threadIdx.x;
    if (i < e) {
        int d = dst[i];
        int p = atomicAdd(&g_cnt[d], 1);
        g_esrc[g_off[d] + p] = src[i];
    }
}

// ---------------------------------------------------------------------------
// Aggregation: warp per dst node in [node0, node0+cnt), single-pass online
// softmax, fp32 h gather.
// ---------------------------------------------------------------------------
__device__ __forceinline__ float leaky02(float x) { return x > 0.f ? x : 0.2f * x; }

template <int HD, int ACT, bool HEADMEAN>
__global__ void agg_kernel(const float* __restrict__ h,
                           const float* __restrict__ res,
                           const float* __restrict__ elp,
                           const float* __restrict__ erp,
                           float* __restrict__ out, int node0, int cnt)
{
    constexpr int V = HD / 32;
    int node = node0 + ((blockIdx.x * blockDim.x + threadIdx.x) >> 5);
    int lane = threadIdx.x & 31;
    if (node >= node0 + cnt) return;

    const int beg = g_off[node];
    const int end = g_off[node + 1];
    const float2 erv = ((const float2*)erp)[node];
    const float2* __restrict__ el2 = (const float2*)elp;
    const int* __restrict__ esrc = g_esrc;

    const bool head0 = (lane * V) < (HD / 2);
    float m0 = -1e30f, m1 = -1e30f;
    float d0 = 0.f, d1 = 0.f;
    float acc[V];
#pragma unroll
    for (int q = 0; q < V; q++) acc[q] = 0.f;

    int i = beg;
    for (; i + 4 <= end; i += 4) {
        int s[4];
#pragma unroll
        for (int j = 0; j < 4; j++) s[j] = esrc[i + j];
        float2 ev[4];
#pragma unroll
        for (int j = 0; j < 4; j++) ev[j] = el2[s[j]];
        float hv[4][V];
#pragma unroll
        for (int j = 0; j < 4; j++) {
            if (V == 4) *(float4*)hv[j] = *(const float4*)(h + (size_t)s[j] * HD + lane * V);
            else        *(float2*)hv[j] = *(const float2*)(h + (size_t)s[j] * HD + lane * V);
        }
#pragma unroll
        for (int j = 0; j < 4; j++) {
            float e0 = leaky02(ev[j].x + erv.x);
            float e1 = leaky02(ev[j].y + erv.y);
            float nm0 = fmaxf(m0, e0), nm1 = fmaxf(m1, e1);
            float sc0 = __expf(m0 - nm0), w0 = __expf(e0 - nm0);
            float sc1 = __expf(m1 - nm1), w1 = __expf(e1 - nm1);
            d0 = d0 * sc0 + w0;
            d1 = d1 * sc1 + w1;
            m0 = nm0; m1 = nm1;
            float scv = head0 ? sc0 : sc1;
            float wv  = head0 ? w0  : w1;
#pragma unroll
            for (int q = 0; q < V; q++) acc[q] = fmaf(acc[q], scv, wv * hv[j][q]);
        }
    }
    for (; i < end; i++) {
        int s = esrc[i];
        float2 ev = el2[s];
        float hv[V];
        if (V == 4) *(float4*)hv = *(const float4*)(h + (size_t)s * HD + lane * V);
        else        *(float2*)hv = *(const float2*)(h + (size_t)s * HD + lane * V);
        float e0 = leaky02(ev.x + erv.x);
        float e1 = leaky02(ev.y + erv.y);
        float nm0 = fmaxf(m0, e0), nm1 = fmaxf(m1, e1);
        float sc0 = __expf(m0 - nm0), w0 = __expf(e0 - nm0);
        float sc1 = __expf(m1 - nm1), w1 = __expf(e1 - nm1);
        d0 = d0 * sc0 + w0;
        d1 = d1 * sc1 + w1;
        m0 = nm0; m1 = nm1;
        float scv = head0 ? sc0 : sc1;
        float wv  = head0 ? w0  : w1;
#pragma unroll
        for (int q = 0; q < V; q++) acc[q] = fmaf(acc[q], scv, wv * hv[q]);
    }

    const bool has = (end > beg);
    const float inv0 = has ? 1.f / d0 : 0.f;
    const float inv1 = has ? 1.f / d1 : 0.f;
    const float invv = head0 ? inv0 : inv1;

    float rr[V];
    if (V == 4) *(float4*)rr = *(const float4*)(res + (size_t)node * HD + lane * V);
    else        *(float2*)rr = *(const float2*)(res + (size_t)node * HD + lane * V);

    float v[V];
#pragma unroll
    for (int q = 0; q < V; q++) {
        v[q] = acc[q] * invv + rr[q];
        if (ACT == 0) v[q] = v[q] > 0.f ? v[q] : expm1f(v[q]);
        else          v[q] = tanhf(v[q]);
    }

    if (HEADMEAN) {
        float p[V];
#pragma unroll
        for (int q = 0; q < V; q++) p[q] = __shfl_xor_sync(0xffffffffu, v[q], 16);
        if (lane < 16) {
            float o[V];
#pragma unroll
            for (int q = 0; q < V; q++) o[q] = 0.5f * (v[q] + p[q]);
            if (V == 4) *(float4*)(out + (size_t)node * 64 + lane * V) = *(float4*)o;
            else        *(float2*)(out + (size_t)node * 64 + lane * V) = *(float2*)o;
        }
    } else {
        if (V == 4) *(float4*)(out + (size_t)node * HD + lane * V) = *(float4*)v;
        else        *(float2*)(out + (size_t)node * HD + lane * V) = *(float2*)v;
    }
}

// ---------------------------------------------------------------------------
// Launch — split pipeline with PING-PONG buffers:
// layer L's gemmF writes buffer L%2, so gemmF(L+1)_A (buffer (L+1)%2) can run
// concurrently with agg(L)_B (reading buffer L%2).
// ---------------------------------------------------------------------------
extern "C" void kernel_launch(void* const* d_in, const int* in_sizes, int n_in,
                              void* d_out, int out_size)
{
    const float* fvs = (const float*)d_in[0];
    const float* pos = (const float*)d_in[1];
    const int*   src = (const int*)d_in[2];
    const int*   dst = (const int*)d_in[3];
    const float* g0W  = (const float*)d_in[4];
    const float* g0al = (const float*)d_in[5];
    const float* g0ar = (const float*)d_in[6];
    const float* g0rW = (const float*)d_in[7];
    const float* g1W  = (const float*)d_in[8];
    const float* g1al = (const float*)d_in[9];
    const float* g1ar = (const float*)d_in[10];
    const float* g1rW = (const float*)d_in[11];
    const float* g2W  = (const float*)d_in[12];
    const float* g2al = (const float*)d_in[13];
    const float* g2ar = (const float*)d_in[14];
    const float* g2rW = (const float*)d_in[15];
    const float* p0W  = (const float*)d_in[16];
    const float* p0al = (const float*)d_in[17];
    const float* p0ar = (const float*)d_in[18];
    const float* p1W  = (const float*)d_in[19];
    const float* p1al = (const float*)d_in[20];
    const float* p1ar = (const float*)d_in[21];

    const int n = in_sizes[0] / 128;
    const int e = in_sizes[2];

    float *hb, *rhb, *elb, *erb, *hs, *hs2, *hp, *hq, *el2, *er2;
    int* cnt;
    uint16_t *wthi, *wtlo;
    cudaGetSymbolAddress((void**)&hb,   g_h);
    cudaGetSymbolAddress((void**)&rhb,  g_rh);
    cudaGetSymbolAddress((void**)&elb,  g_el);
    cudaGetSymbolAddress((void**)&erb,  g_er);
    cudaGetSymbolAddress((void**)&hs,   g_hs);
    cudaGetSymbolAddress((void**)&hs2,  g_hs2);
    cudaGetSymbolAddress((void**)&hp,   g_hp);
    cudaGetSymbolAddress((void**)&hq,   g_hq);
    cudaGetSymbolAddress((void**)&el2,  g_el2);
    cudaGetSymbolAddress((void**)&er2,  g_er2);
    cudaGetSymbolAddress((void**)&cnt,  g_cnt);
    cudaGetSymbolAddress((void**)&wthi, g_wthi);
    cudaGetSymbolAddress((void**)&wtlo, g_wtlo);

    // ping-pong buffer pointers
    float* h0  = hb;                       float* h1  = hb  + (size_t)NMAX * 128;
    float* rh0 = rhb;                      float* rh1 = rhb + (size_t)NMAX * 128;
    float* el0 = elb;                      float* el1 = elb + (size_t)NMAX * 2;
    float* er0 = erb;                      float* er1 = erb + (size_t)NMAX * 2;

    float* out_hs = (float*)d_out;
    float* out_hp = (float*)d_out + (size_t)n * 64;

    const int EB = (e + 255) / 256;
    const int GB = (n + 127) / 128;
    const int WB = (n + 7) / 8;

    const int halfA = ((n / 2 + 127) / 128) * 128;
    const int cntB  = n - halfA;
    const int GBA = (halfA + 127) / 128;
    const int GBB = (cntB + 127) / 128;
    const int WBA = (halfA + 7) / 8;
    const int WBB = (cntB + 7) / 8;

    constexpr int SMEM_F     = 2 * 128 * 384 + 256 * 384;
    constexpr int SMEM_SMALL = (128 + 128 + 64 + 64) * 64 * 2;
    cudaFuncSetAttribute(tc_gemm_fused<192>,    cudaFuncAttributeMaxDynamicSharedMemorySize, SMEM_F);
    cudaFuncSetAttribute(tc_gemm_small<64, 64>, cudaFuncAttributeMaxDynamicSharedMemorySize, SMEM_SMALL);

    static cudaStream_t s1 = nullptr, s2 = nullptr, s3 = nullptr;
    static cudaEvent_t evFork, evPrep, evCSR, evP0, evP1;
    static cudaEvent_t evA0A, evA0B, evA1A, evA1B, evEnd1, evEnd2;
    if (s1 == nullptr) {
        cudaStreamCreateWithFlags(&s1, cudaStreamNonBlocking);
        cudaStreamCreateWithFlags(&s2, cudaStreamNonBlocking);
        cudaStreamCreateWithFlags(&s3, cudaStreamNonBlocking);
        cudaEventCreateWithFlags(&evFork, cudaEventDisableTiming);
        cudaEventCreateWithFlags(&evPrep, cudaEventDisableTiming);
        cudaEventCreateWithFlags(&evCSR,  cudaEventDisableTiming);
        cudaEventCreateWithFlags(&evP0,   cudaEventDisableTiming);
        cudaEventCreateWithFlags(&evP1,   cudaEventDisableTiming);
        cudaEventCreateWithFlags(&evA0A,  cudaEventDisableTiming);
        cudaEventCreateWithFlags(&evA0B,  cudaEventDisableTiming);
        cudaEventCreateWithFlags(&evA1A,  cudaEventDisableTiming);
        cudaEventCreateWithFlags(&evA1B,  cudaEventDisableTiming);
        cudaEventCreateWithFlags(&evEnd1, cudaEventDisableTiming);
        cudaEventCreateWithFlags(&evEnd2, cudaEventDisableTiming);
    }

    Prep8 pa;
    const float* Ws[8] = {g0W, g0rW, g1W, g1rW, g2W, g2rW, p0W, p1W};
    for (int m = 0; m < 8; m++) {
        pa.W[m] = Ws[m];
        pa.K[m] = (m < 6) ? 192 : 64;
        pa.N[m] = (m < 6) ? 128 : 64;
        pa.off[m] = (m < 6) ? (m >> 1) * WT_FUSED + (m & 1) * (128 * 192)
                            : 3 * WT_FUSED + (m - 6) * WT_SMALL;
    }

    const int F0 = 0 * WT_FUSED, F1 = 1 * WT_FUSED, F2 = 2 * WT_FUSED;
    const int P0 = 3 * WT_FUSED, P1 = 3 * WT_FUSED + WT_SMALL;

    // ---- fork ----
    cudaEventRecord(evFork, 0);
    cudaStreamWaitEvent(s1, evFork, 0);
    cudaStreamWaitEvent(s2, evFork, 0);
    cudaStreamWaitEvent(s3, evFork, 0);

    prep_kernel<<<64, 256, 0, s1>>>(pa);
    cudaEventRecord(evPrep, s1);
    cudaStreamWaitEvent(s2, evPrep, 0);

    // s0: CSR build (hidden under prep + gemmF0)
    cudaMemsetAsync(cnt, 0, (size_t)n * sizeof(int), 0);
    count_kernel<<<EB, 256, 0, 0>>>(dst, e);
    scan_kernel<<<1, 1024, 0, 0>>>(n);
    fill_kernel<<<EB, 256, 0, 0>>>(src, dst, e);
    cudaEventRecord(evCSR, 0);

    // ---- layer 0 GEMMs (buffer 0) ----
    tc_gemm_fused<192><<<GB, 256, SMEM_F, s1>>>(fvs, 128, pos, wthi + F0, wtlo + F0,
                                                g0al, g0ar, el0, er0, h0, rh0, n, 0);
    tc_gemm_small<64, 64><<<GB, 256, SMEM_SMALL, s2>>>(pos, wthi + P0, wtlo + P0,
                                                       p0al, p0ar, el2, er2, hq, n);
    cudaStreamWaitEvent(s2, evCSR, 0);
    agg_kernel<64, 1, false><<<WB, 256, 0, s2>>>(hq, pos, el2, er2, hp, 0, n);
    cudaEventRecord(evP0, s2);

    // ---- boundary 0: agg0 (reads buf0) split; gemmF1 (writes buf1) split ----
    cudaStreamWaitEvent(s1, evCSR, 0);
    agg_kernel<128, 0, false><<<WBA, 256, 0, s1>>>(h0, rh0, el0, er0, hs, 0, halfA);
    cudaEventRecord(evA0A, s1);
    cudaStreamWaitEvent(s3, evA0A, 0);
    agg_kernel<128, 0, false><<<WBB, 256, 0, s3>>>(h0, rh0, el0, er0, hs, halfA, cntB);
    cudaEventRecord(evA0B, s3);

    cudaStreamWaitEvent(s1, evP0, 0);    // gemmF1 needs hp
    // gemmF1_A: reads hs[0,halfA) (done by agg0A), writes buf1 — runs ∥ agg0B
    tc_gemm_fused<192><<<GBA, 256, SMEM_F, s1>>>(hs, 128, hp, wthi + F1, wtlo + F1,
                                                 g1al, g1ar, el1, er1, h1, rh1, n, 0);
    cudaStreamWaitEvent(s1, evA0B, 0);   // gemmF1_B reads hs[halfA..) from agg0B
    tc_gemm_fused<192><<<GBB, 256, SMEM_F, s1>>>(hs, 128, hp, wthi + F1, wtlo + F1,
                                                 g1al, g1ar, el1, er1, h1, rh1, n, halfA);

    // pg layer 1 (s2, overlaps boundary 0)
    tc_gemm_small<64, 64><<<GB, 256, SMEM_SMALL, s2>>>(hp, wthi + P1, wtlo + P1,
                                                       p1al, p1ar, el2, er2, hq, n);
    agg_kernel<64, 1, false><<<WB, 256, 0, s2>>>(hq, hp, el2, er2, out_hp, 0, n);
    cudaEventRecord(evP1, s2);

    // ---- boundary 1: agg1 (reads buf1, needs BOTH gemmF1 halves) split ----
    agg_kernel<128, 0, false><<<WBA, 256, 0, s1>>>(h1, rh1, el1, er1, hs2, 0, halfA);
    cudaEventRecord(evA1A, s1);
    cudaStreamWaitEvent(s3, evA1A, 0);
    agg_kernel<128, 0, false><<<WBB, 256, 0, s3>>>(h1, rh1, el1, er1, hs2, halfA, cntB);
    cudaEventRecord(evA1B, s3);

    cudaStreamWaitEvent(s1, evP1, 0);    // gemmF2 needs out_hp
    // gemmF2_A: reads hs2[0,halfA), writes buf0 — runs ∥ agg1B (reads buf1)
    tc_gemm_fused<192><<<GBA, 256, SMEM_F, s1>>>(hs2, 128, out_hp, wthi + F2, wtlo + F2,
                                                 g2al, g2ar, el0, er0, h0, rh0, n, 0);
    cudaStreamWaitEvent(s1, evA1B, 0);
    tc_gemm_fused<192><<<GBB, 256, SMEM_F, s1>>>(hs2, 128, out_hp, wthi + F2, wtlo + F2,
                                                 g2al, g2ar, el0, er0, h0, rh0, n, halfA);

    // ---- final agg (headmean, reads buf0, needs both gemmF2 halves) ----
    agg_kernel<128, 0, true><<<WB, 256, 0, s1>>>(h0, rh0, el0, er0, out_hs, 0, n);
    cudaEventRecord(evEnd1, s1);
    cudaEventRecord(evEnd2, s2);

    // ---- join ----
    cudaStreamWaitEvent(0, evEnd1, 0);
    cudaStreamWaitEvent(0, evEnd2, 0);
}

// round 14
// speedup vs baseline: 1.4916x; 1.0600x over previous
#include <cuda_runtime.h>
#include <cuda_bf16.h>
#include <math.h>
#include <stdint.h>

// ---------------------------------------------------------------------------
// Problem constants
// ---------------------------------------------------------------------------
#define NMAX 50000
#define EMAX 800000

// ---------------------------------------------------------------------------
// Scratch (device globals) — gat-chain h/rh/el/er double-buffered.
// ---------------------------------------------------------------------------
__device__ float g_h  [2][(size_t)NMAX * 128];
__device__ float g_rh [2][(size_t)NMAX * 128];
__device__ float g_el [2][(size_t)NMAX * 2];
__device__ float g_er [2][(size_t)NMAX * 2];
__device__ float g_hs [(size_t)NMAX * 128];
__device__ float g_hs2[(size_t)NMAX * 128];
__device__ float g_hp [(size_t)NMAX * 64];
__device__ float g_hq [(size_t)NMAX * 64];
__device__ float g_el2[(size_t)NMAX * 2];
__device__ float g_er2[(size_t)NMAX * 2];
__device__ int   g_off[NMAX + 1];
__device__ int   g_cnt[NMAX];
__device__ int   g_esrc[EMAX];

#define WT_FUSED (256 * 192)
#define WT_SMALL (64 * 64)
__device__ uint16_t g_wthi[3 * WT_FUSED + 2 * WT_SMALL];
__device__ uint16_t g_wtlo[3 * WT_FUSED + 2 * WT_SMALL];

// ---------------------------------------------------------------------------
// Helpers
// ---------------------------------------------------------------------------
__device__ __forceinline__ uint32_t smem_u32(const void* p) {
    uint32_t a;
    asm("{ .reg .u64 t; cvta.to.shared.u64 t, %1; cvt.u32.u64 %0, t; }"
        : "=r"(a) : "l"(p));
    return a;
}

__device__ __forceinline__ void ldsm_x4(uint32_t* r, uint32_t addr) {
    asm volatile("ldmatrix.sync.aligned.m8n8.x4.shared.b16 {%0,%1,%2,%3}, [%4];"
                 : "=r"(r[0]), "=r"(r[1]), "=r"(r[2]), "=r"(r[3]) : "r"(addr));
}

__device__ __forceinline__ void mma16816(float* c, const uint32_t* a, const uint32_t* b) {
    asm volatile(
        "mma.sync.aligned.m16n8k16.row.col.f32.bf16.bf16.f32 "
        "{%0,%1,%2,%3}, {%4,%5,%6,%7}, {%8,%9}, {%0,%1,%2,%3};"
        : "+f"(c[0]), "+f"(c[1]), "+f"(c[2]), "+f"(c[3])
        : "r"(a[0]), "r"(a[1]), "r"(a[2]), "r"(a[3]), "r"(b[0]), "r"(b[1]));
}

__device__ __forceinline__ void cpasync16(uint32_t s, const void* g) {
    asm volatile("cp.async.cg.shared.global [%0], [%1], 16;" :: "r"(s), "l"(g));
}
__device__ __forceinline__ void cpasync_wait() {
    asm volatile("cp.async.commit_group;");
    asm volatile("cp.async.wait_group 0;" ::: "memory");
}

__device__ __forceinline__ void split8(const float* v, uint4& h4, uint4& l4) {
    uint16_t* hp = (uint16_t*)&h4;
    uint16_t* lp = (uint16_t*)&l4;
#pragma unroll
    for (int i = 0; i < 8; i++) {
        __nv_bfloat16 hb = __float2bfloat16(v[i]);
        float r = v[i] - __bfloat162float(hb);
        __nv_bfloat16 lb = __float2bfloat16(r);
        hp[i] = *(uint16_t*)&hb;
        lp[i] = *(uint16_t*)&lb;
    }
}

__device__ __forceinline__ uint32_t swz(int row, int g, int ROWB) {
    int c = (g & ~7) | ((g ^ row) & 7);
    return (uint32_t)(row * ROWB + c * 16);
}

// ---------------------------------------------------------------------------
// Weight prep
// ---------------------------------------------------------------------------
struct Prep8 {
    const float* W[8];
    int K[8], N[8], off[8];
};

__global__ void prep_kernel(Prep8 p) {
    for (int m = 0; m < 8; m++) {
        const int K = p.K[m], N = p.N[m], tot = K * N, off = p.off[m];
        const float* W = p.W[m];
        for (int idx = blockIdx.x * blockDim.x + threadIdx.x; idx < tot;
             idx += gridDim.x * blockDim.x) {
            int n = idx / K, k = idx - n * K;
            float w = W[(size_t)k * N + n];
            __nv_bfloat16 h = __float2bfloat16(w);
            float r = w - __bfloat162float(h);
            __nv_bfloat16 l = __float2bfloat16(r);
            g_wthi[off + idx] = *(uint16_t*)&h;
            g_wtlo[off + idx] = *(uint16_t*)&l;
        }
    }
}

// ---------------------------------------------------------------------------
// Fused bf16x3 GEMM + el/er epilogue (gat chain). row0 = M-tile base offset.
// ---------------------------------------------------------------------------
template <int K>
__global__ __launch_bounds__(256, 1) void tc_gemm_fused(
    const float* __restrict__ A1, int K1,
    const float* __restrict__ A2,
    const uint16_t* __restrict__ Bh, const uint16_t* __restrict__ Bl,
    const float* __restrict__ al, const float* __restrict__ ar,
    float* __restrict__ el, float* __restrict__ er,
    float* __restrict__ C1, float* __restrict__ C2, int M, int row0)
{
    constexpr int BN   = 256;
    constexpr int ROWB = K * 2;
    constexpr int NG   = K / 8;
    constexpr int WN   = 128;
    constexpr int NT   = WN / 8;
    constexpr int KS   = K / 16;
    constexpr int AOFF  = 0;
    constexpr int ALOFF = 128 * ROWB;
    constexpr int BOFF  = 2 * 128 * ROWB;

    extern __shared__ char smem[];
    const uint32_t sb  = smem_u32(smem);
    const uint32_t sAH = sb + AOFF;
    const uint32_t sAL = sb + ALOFF;
    const uint32_t sB  = sb + BOFF;

    const int t    = threadIdx.x;
    const int wid  = t >> 5;
    const int lane = t & 31;
    const int bm   = row0 + blockIdx.x * 128;

    for (int idx = t; idx < BN * NG; idx += 256) {
        int rn = idx / NG, g = idx - rn * NG;
        cpasync16(sB + swz(rn, g, ROWB), Bh + (size_t)rn * K + g * 8);
    }

    for (int idx = t; idx < 128 * NG; idx += 256) {
        int row = idx / NG, g = idx - row * NG, k0 = g * 8;
        int grow = bm + row;
        float v[8] = {0, 0, 0, 0, 0, 0, 0, 0};
        if (grow < M) {
            const float* p = (k0 < K1) ? (A1 + (size_t)grow * K1 + k0)
                                       : (A2 + (size_t)grow * (K - K1) + (k0 - K1));
            *(float4*)&v[0] = ((const float4*)p)[0];
            *(float4*)&v[4] = ((const float4*)p)[1];
        }
        uint4 h4, l4;
        split8(v, h4, l4);
        uint32_t o = swz(row, g, ROWB);
        *(uint4*)(smem + AOFF + o)  = h4;
        *(uint4*)(smem + ALOFF + o) = l4;
    }
    cpasync_wait();
    __syncthreads();

    const int wm   = wid & 3;
    const int wn   = wid >> 2;
    const int lr   = lane & 7;
    const int sel  = lane >> 3;
    const int selb1 = sel & 1;
    const int selb2 = sel >> 1;
    const int rowA_base = wm * 32 + lr + selb1 * 8;
    const int rowB_base = wn * WN + lr + selb2 * 8;

    float acc[2][NT][4];
#pragma unroll
    for (int mt = 0; mt < 2; mt++)
#pragma unroll
        for (int nt = 0; nt < NT; nt++)
#pragma unroll
            for (int q = 0; q < 4; q++) acc[mt][nt][q] = 0.f;

#pragma unroll
    for (int ks = 0; ks < KS; ks++) {
        uint32_t bfr[NT][2];
#pragma unroll
        for (int nt2 = 0; nt2 < NT / 2; nt2++) {
            uint32_t r[4];
            ldsm_x4(r, sB + swz(rowB_base + nt2 * 16, ks * 2 + selb1, ROWB));
            bfr[2 * nt2][0]     = r[0];
            bfr[2 * nt2][1]     = r[1];
            bfr[2 * nt2 + 1][0] = r[2];
            bfr[2 * nt2 + 1][1] = r[3];
        }
        uint32_t afr[2][4];
#pragma unroll
        for (int mt = 0; mt < 2; mt++)
            ldsm_x4(afr[mt], sAH + swz(rowA_base + mt * 16, ks * 2 + selb2, ROWB));
#pragma unroll
        for (int mt = 0; mt < 2; mt++)
#pragma unroll
            for (int nt = 0; nt < NT; nt++)
                mma16816(acc[mt][nt], afr[mt], bfr[nt]);
#pragma unroll
        for (int mt = 0; mt < 2; mt++)
            ldsm_x4(afr[mt], sAL + swz(rowA_base + mt * 16, ks * 2 + selb2, ROWB));
#pragma unroll
        for (int mt = 0; mt < 2; mt++)
#pragma unroll
            for (int nt = 0; nt < NT; nt++)
                mma16816(acc[mt][nt], afr[mt], bfr[nt]);
    }

    __syncthreads();
    for (int idx = t; idx < BN * NG; idx += 256) {
        int rn = idx / NG, g = idx - rn * NG;
        cpasync16(sB + swz(rn, g, ROWB), Bl + (size_t)rn * K + g * 8);
    }
    cpasync_wait();
    __syncthreads();

#pragma unroll
    for (int ks = 0; ks < KS; ks++) {
        uint32_t bfr[NT][2];
#pragma unroll
        for (int nt2 = 0; nt2 < NT / 2; nt2++) {
            uint32_t r[4];
            ldsm_x4(r, sB + swz(rowB_base + nt2 * 16, ks * 2 + selb1, ROWB));
            bfr[2 * nt2][0]     = r[0];
            bfr[2 * nt2][1]     = r[1];
            bfr[2 * nt2 + 1][0] = r[2];
            bfr[2 * nt2 + 1][1] = r[3];
        }
        uint32_t afr[2][4];
#pragma unroll
        for (int mt = 0; mt < 2; mt++)
            ldsm_x4(afr[mt], sAH + swz(rowA_base + mt * 16, ks * 2 + selb2, ROWB));
#pragma unroll
        for (int mt = 0; mt < 2; mt++)
#pragma unroll
            for (int nt = 0; nt < NT; nt++)
                mma16816(acc[mt][nt], afr[mt], bfr[nt]);
    }

    float* __restrict__ C = (wn == 0) ? C1 : C2;
    const int colb = (lane & 3) * 2;
#pragma unroll
    for (int mt = 0; mt < 2; mt++) {
        int r0 = bm + wm * 32 + mt * 16 + (lane >> 2);
        int r1 = r0 + 8;
#pragma unroll
        for (int nt = 0; nt < NT; nt++) {
            int col = colb + nt * 8;
            if (r0 < M) *(float2*)&C[(size_t)r0 * 128 + col] =
                make_float2(acc[mt][nt][0], acc[mt][nt][1]);
            if (r1 < M) *(float2*)&C[(size_t)r1 * 128 + col] =
                make_float2(acc[mt][nt][2], acc[mt][nt][3]);
        }
    }

    if (wn == 0) {
#pragma unroll
        for (int mt = 0; mt < 2; mt++) {
            float e[8];
#pragma unroll
            for (int q = 0; q < 8; q++) e[q] = 0.f;
#pragma unroll
            for (int nt = 0; nt < NT; nt++) {
                int c = colb + nt * 8;
                float a0 = al[c], a1 = al[c + 1];
                float b0 = ar[c], b1 = ar[c + 1];
                float sl0 = acc[mt][nt][0] * a0 + acc[mt][nt][1] * a1;
                float sl1 = acc[mt][nt][2] * a0 + acc[mt][nt][3] * a1;
                float sr0 = acc[mt][nt][0] * b0 + acc[mt][nt][1] * b1;
                float sr1 = acc[mt][nt][2] * b0 + acc[mt][nt][3] * b1;
                int hsel = (nt < 8) ? 0 : 1;
                e[hsel]     += sl0;
                e[2 + hsel] += sr0;
                e[4 + hsel] += sl1;
                e[6 + hsel] += sr1;
            }
#pragma unroll
            for (int o = 1; o <= 2; o <<= 1)
#pragma unroll
                for (int q = 0; q < 8; q++)
                    e[q] += __shfl_xor_sync(0xffffffffu, e[q], o);
            if ((lane & 3) == 0) {
                int r0 = bm + wm * 32 + mt * 16 + (lane >> 2);
                int r1 = r0 + 8;
                if (r0 < M) {
                    el[2 * r0] = e[0]; el[2 * r0 + 1] = e[1];
                    er[2 * r0] = e[2]; er[2 * r0 + 1] = e[3];
                }
                if (r1 < M) {
                    el[2 * r1] = e[4]; el[2 * r1 + 1] = e[5];
                    er[2 * r1] = e[6]; er[2 * r1 + 1] = e[7];
                }
            }
        }
    }
}

// ---------------------------------------------------------------------------
// Small bf16x3 GEMM (pg layers) with fused el/er epilogue
// ---------------------------------------------------------------------------
template <int BN, int K>
__global__ __launch_bounds__(256, 1) void tc_gemm_small(
    const float* __restrict__ A1,
    const uint16_t* __restrict__ Bh, const uint16_t* __restrict__ Bl,
    const float* __restrict__ al, const float* __restrict__ ar,
    float* __restrict__ el, float* __restrict__ er,
    float* __restrict__ C, int M)
{
    constexpr int ROWB = K * 2;
    constexpr int NG   = K / 8;
    constexpr int WN   = BN / 2;
    constexpr int NT   = WN / 8;
    constexpr int KS   = K / 16;

    extern __shared__ char smem[];
    const uint32_t sAH = smem_u32(smem);
    const uint32_t sAL = sAH + 128 * ROWB;
    const uint32_t sBH = sAL + 128 * ROWB;
    const uint32_t sBL = sBH + BN * ROWB;

    const int t    = threadIdx.x;
    const int wid  = t >> 5;
    const int lane = t & 31;
    const int bm   = blockIdx.x * 128;

    for (int idx = t; idx < BN * NG; idx += 256) {
        int rn = idx / NG, g = idx - rn * NG, k0 = g * 8;
        cpasync16(sBH + swz(rn, g, ROWB), Bh + (size_t)rn * K + k0);
        cpasync16(sBL + swz(rn, g, ROWB), Bl + (size_t)rn * K + k0);
    }
    for (int idx = t; idx < 128 * NG; idx += 256) {
        int row = idx / NG, g = idx - row * NG, k0 = g * 8;
        int grow = bm + row;
        float v[8] = {0, 0, 0, 0, 0, 0, 0, 0};
        if (grow < M) {
            const float* p = A1 + (size_t)grow * K + k0;
            *(float4*)&v[0] = ((const float4*)p)[0];
            *(float4*)&v[4] = ((const float4*)p)[1];
        }
        uint4 h4, l4;
        split8(v, h4, l4);
        uint32_t o = swz(row, g, ROWB);
        *(uint4*)(smem + o) = h4;
        *(uint4*)(smem + 128 * ROWB + o) = l4;
    }
    cpasync_wait();
    __syncthreads();

    const int wm = wid & 3;
    const int wn = wid >> 2;
    const int lr   = lane & 7;
    const int sel  = lane >> 3;
    const int selb1 = sel & 1;
    const int selb2 = sel >> 1;
    const int rowA_base = wm * 32 + lr + selb1 * 8;
    const int rowB_base = wn * WN + lr + selb2 * 8;

    float acc[2][NT][4];
#pragma unroll
    for (int mt = 0; mt < 2; mt++)
#pragma unroll
        for (int nt = 0; nt < NT; nt++)
#pragma unroll
            for (int q = 0; q < 4; q++) acc[mt][nt][q] = 0.f;

#pragma unroll
    for (int pr = 0; pr < 3; pr++) {
        const uint32_t baseA = (pr == 2) ? sAL : sAH;
        const uint32_t baseB = (pr == 1) ? sBL : sBH;
#pragma unroll
        for (int ks = 0; ks < KS; ks++) {
            uint32_t afr[2][4];
#pragma unroll
            for (int mt = 0; mt < 2; mt++)
                ldsm_x4(afr[mt], baseA + swz(rowA_base + mt * 16, ks * 2 + selb2, ROWB));
            uint32_t bfr[NT][2];
#pragma unroll
            for (int nt2 = 0; nt2 < NT / 2; nt2++) {
                uint32_t r[4];
                ldsm_x4(r, baseB + swz(rowB_base + nt2 * 16, ks * 2 + selb1, ROWB));
                bfr[2 * nt2][0]     = r[0];
                bfr[2 * nt2][1]     = r[1];
                bfr[2 * nt2 + 1][0] = r[2];
                bfr[2 * nt2 + 1][1] = r[3];
            }
#pragma unroll
            for (int mt = 0; mt < 2; mt++)
#pragma unroll
                for (int nt = 0; nt < NT; nt++)
                    mma16816(acc[mt][nt], afr[mt], bfr[nt]);
        }
    }

    const int colb = wn * WN + (lane & 3) * 2;
#pragma unroll
    for (int mt = 0; mt < 2; mt++) {
        int r0 = bm + wm * 32 + mt * 16 + (lane >> 2);
        int r1 = r0 + 8;
#pragma unroll
        for (int nt = 0; nt < NT; nt++) {
            int col = colb + nt * 8;
            if (r0 < M) *(float2*)&C[(size_t)r0 * BN + col] =
                make_float2(acc[mt][nt][0], acc[mt][nt][1]);
            if (r1 < M) *(float2*)&C[(size_t)r1 * BN + col] =
                make_float2(acc[mt][nt][2], acc[mt][nt][3]);
        }
    }

#pragma unroll
    for (int mt = 0; mt < 2; mt++) {
        float e[4];
#pragma unroll
        for (int q = 0; q < 4; q++) e[q] = 0.f;
#pragma unroll
        for (int nt = 0; nt < NT; nt++) {
            int c = colb + nt * 8;
            float a0 = al[c], a1 = al[c + 1];
            float b0 = ar[c], b1 = ar[c + 1];
            e[0] += acc[mt][nt][0] * a0 + acc[mt][nt][1] * a1;
            e[1] += acc[mt][nt][0] * b0 + acc[mt][nt][1] * b1;
            e[2] += acc[mt][nt][2] * a0 + acc[mt][nt][3] * a1;
            e[3] += acc[mt][nt][2] * b0 + acc[mt][nt][3] * b1;
        }
#pragma unroll
        for (int o = 1; o <= 2; o <<= 1)
#pragma unroll
            for (int q = 0; q < 4; q++)
                e[q] += __shfl_xor_sync(0xffffffffu, e[q], o);
        if ((lane & 3) == 0) {
            int r0 = bm + wm * 32 + mt * 16 + (lane >> 2);
            int r1 = r0 + 8;
            if (r0 < M) { el[2 * r0 + wn] = e[0]; er[2 * r0 + wn] = e[1]; }
            if (r1 < M) { el[2 * r1 + wn] = e[2]; er[2 * r1 + wn] = e[3]; }
        }
    }
}

// ---------------------------------------------------------------------------
// CSR build
// ---------------------------------------------------------------------------
__global__ void count_kernel(const int* __restrict__ dst, int e) {
    int i = blockIdx.x * blockDim.x + threadIdx.x;
    if (i < e) atomicAdd(&g_cnt[dst[i]], 1);
}

__global__ void scan_kernel(int n) {
    __shared__ int partial[1024];
    const int t = threadIdx.x;
    const int C = (n + 1023) / 1024;
    int s = 0;
    for (int j = 0; j < C; j++) {
        int idx = t * C + j;
        if (idx < n) s += g_cnt[idx];
    }
    partial[t] = s;
    __syncthreads();
    for (int ofs = 1; ofs < 1024; ofs <<= 1) {
        int v = (t >= ofs) ? partial[t - ofs] : 0;
        __syncthreads();
        partial[t] += v;
        __syncthreads();
    }
    int run = (t == 0) ? 0 : partial[t - 1];
    for (int j = 0; j < C; j++) {
        int idx = t * C + j;
        if (idx < n) {
            g_off[idx] = run;
            run += g_cnt[idx];
            g_cnt[idx] = 0;
        }
    }
    if (t == 1023) g_off[n] = run;
}

__global__ void fill_kernel(const int* __restrict__ src, const int* __restrict__ dst, int e) {
    int i = blockIdx.x * blockDim.x + threadIdx.x;
    if (i < e) {
        int d = dst[i];
        int p = atomicAdd(&g_cnt[d], 1);
        g_esrc[g_off[d] + p] = src[i];
    }
}

// ---------------------------------------------------------------------------
// Aggregation: warp per dst node in [node0, node0+cnt), single-pass online
// softmax, fp32 h gather.
// ---------------------------------------------------------------------------
__device__ __forceinline__ float leaky02(float x) { return x > 0.f ? x : 0.2f * x; }

template <int HD, int ACT, bool HEADMEAN>
__global__ void agg_kernel(const float* __restrict__ h,
                           const float* __restrict__ res,
                           const float* __restrict__ elp,
                           const float* __restrict__ erp,
                           float* __restrict__ out, int node0, int cnt)
{
    constexpr int V = HD / 32;
    int node = node0 + ((blockIdx.x * blockDim.x + threadIdx.x) >> 5);
    int lane = threadIdx.x & 31;
    if (node >= node0 + cnt) return;

    const int beg = g_off[node];
    const int end = g_off[node + 1];
    const float2 erv = ((const float2*)erp)[node];
    const float2* __restrict__ el2 = (const float2*)elp;
    const int* __restrict__ esrc = g_esrc;

    const bool head0 = (lane * V) < (HD / 2);
    float m0 = -1e30f, m1 = -1e30f;
    float d0 = 0.f, d1 = 0.f;
    float acc[V];
#pragma unroll
    for (int q = 0; q < V; q++) acc[q] = 0.f;

    int i = beg;
    for (; i + 4 <= end; i += 4) {
        int s[4];
#pragma unroll
        for (int j = 0; j < 4; j++) s[j] = esrc[i + j];
        float2 ev[4];
#pragma unroll
        for (int j = 0; j < 4; j++) ev[j] = el2[s[j]];
        float hv[4][V];
#pragma unroll
        for (int j = 0; j < 4; j++) {
            if (V == 4) *(float4*)hv[j] = *(const float4*)(h + (size_t)s[j] * HD + lane * V);
            else        *(float2*)hv[j] = *(const float2*)(h + (size_t)s[j] * HD + lane * V);
        }
#pragma unroll
        for (int j = 0; j < 4; j++) {
            float e0 = leaky02(ev[j].x + erv.x);
            float e1 = leaky02(ev[j].y + erv.y);
            float nm0 = fmaxf(m0, e0), nm1 = fmaxf(m1, e1);
            float sc0 = __expf(m0 - nm0), w0 = __expf(e0 - nm0);
            float sc1 = __expf(m1 - nm1), w1 = __expf(e1 - nm1);
            d0 = d0 * sc0 + w0;
            d1 = d1 * sc1 + w1;
            m0 = nm0; m1 = nm1;
            float scv = head0 ? sc0 : sc1;
            float wv  = head0 ? w0  : w1;
#pragma unroll
            for (int q = 0; q < V; q++) acc[q] = fmaf(acc[q], scv, wv * hv[j][q]);
        }
    }
    for (; i < end; i++) {
        int s = esrc[i];
        float2 ev = el2[s];
        float hv[V];
        if (V == 4) *(float4*)hv = *(const float4*)(h + (size_t)s * HD + lane * V);
        else        *(float2*)hv = *(const float2*)(h + (size_t)s * HD + lane * V);
        float e0 = leaky02(ev.x + erv.x);
        float e1 = leaky02(ev.y + erv.y);
        float nm0 = fmaxf(m0, e0), nm1 = fmaxf(m1, e1);
        float sc0 = __expf(m0 - nm0), w0 = __expf(e0 - nm0);
        float sc1 = __expf(m1 - nm1), w1 = __expf(e1 - nm1);
        d0 = d0 * sc0 + w0;
        d1 = d1 * sc1 + w1;
        m0 = nm0; m1 = nm1;
        float scv = head0 ? sc0 : sc1;
        float wv  = head0 ? w0  : w1;
#pragma unroll
        for (int q = 0; q < V; q++) acc[q] = fmaf(acc[q], scv, wv * hv[q]);
    }

    const bool has = (end > beg);
    const float inv0 = has ? 1.f / d0 : 0.f;
    const float inv1 = has ? 1.f / d1 : 0.f;
    const float invv = head0 ? inv0 : inv1;

    float rr[V];
    if (V == 4) *(float4*)rr = *(const float4*)(res + (size_t)node * HD + lane * V);
    else        *(float2*)rr = *(const float2*)(res + (size_t)node * HD + lane * V);

    float v[V];
#pragma unroll
    for (int q = 0; q < V; q++) {
        v[q] = acc[q] * invv + rr[q];
        if (ACT == 0) v[q] = v[q] > 0.f ? v[q] : expm1f(v[q]);
        else          v[q] = tanhf(v[q]);
    }

    if (HEADMEAN) {
        float p[V];
#pragma unroll
        for (int q = 0; q < V; q++) p[q] = __shfl_xor_sync(0xffffffffu, v[q], 16);
        if (lane < 16) {
            float o[V];
#pragma unroll
            for (int q = 0; q < V; q++) o[q] = 0.5f * (v[q] + p[q]);
            if (V == 4) *(float4*)(out + (size_t)node * 64 + lane * V) = *(float4*)o;
            else        *(float2*)(out + (size_t)node * 64 + lane * V) = *(float2*)o;
        }
    } else {
        if (V == 4) *(float4*)(out + (size_t)node * HD + lane * V) = *(float4*)v;
        else        *(float2*)(out + (size_t)node * HD + lane * V) = *(float2*)v;
    }
}

// ---------------------------------------------------------------------------
// Launch — 3-stage chunked agg→gemm pipeline per boundary, ping-pong buffers.
// s1 = gemm chain, s3 = agg chunks, s2 = pg chain, s0 = CSR.
// ---------------------------------------------------------------------------
extern "C" void kernel_launch(void* const* d_in, const int* in_sizes, int n_in,
                              void* d_out, int out_size)
{
    const float* fvs = (const float*)d_in[0];
    const float* pos = (const float*)d_in[1];
    const int*   src = (const int*)d_in[2];
    const int*   dst = (const int*)d_in[3];
    const float* g0W  = (const float*)d_in[4];
    const float* g0al = (const float*)d_in[5];
    const float* g0ar = (const float*)d_in[6];
    const float* g0rW = (const float*)d_in[7];
    const float* g1W  = (const float*)d_in[8];
    const float* g1al = (const float*)d_in[9];
    const float* g1ar = (const float*)d_in[10];
    const float* g1rW = (const float*)d_in[11];
    const float* g2W  = (const float*)d_in[12];
    const float* g2al = (const float*)d_in[13];
    const float* g2ar = (const float*)d_in[14];
    const float* g2rW = (const float*)d_in[15];
    const float* p0W  = (const float*)d_in[16];
    const float* p0al = (const float*)d_in[17];
    const float* p0ar = (const float*)d_in[18];
    const float* p1W  = (const float*)d_in[19];
    const float* p1al = (const float*)d_in[20];
    const float* p1ar = (const float*)d_in[21];

    const int n = in_sizes[0] / 128;
    const int e = in_sizes[2];

    float *hb, *rhb, *elb, *erb, *hs, *hs2, *hp, *hq, *el2, *er2;
    int* cnt;
    uint16_t *wthi, *wtlo;
    cudaGetSymbolAddress((void**)&hb,   g_h);
    cudaGetSymbolAddress((void**)&rhb,  g_rh);
    cudaGetSymbolAddress((void**)&elb,  g_el);
    cudaGetSymbolAddress((void**)&erb,  g_er);
    cudaGetSymbolAddress((void**)&hs,   g_hs);
    cudaGetSymbolAddress((void**)&hs2,  g_hs2);
    cudaGetSymbolAddress((void**)&hp,   g_hp);
    cudaGetSymbolAddress((void**)&hq,   g_hq);
    cudaGetSymbolAddress((void**)&el2,  g_el2);
    cudaGetSymbolAddress((void**)&er2,  g_er2);
    cudaGetSymbolAddress((void**)&cnt,  g_cnt);
    cudaGetSymbolAddress((void**)&wthi, g_wthi);
    cudaGetSymbolAddress((void**)&wtlo, g_wtlo);

    float* h0  = hb;                       float* h1  = hb  + (size_t)NMAX * 128;
    float* rh0 = rhb;                      float* rh1 = rhb + (size_t)NMAX * 128;
    float* el0 = elb;                      float* el1 = elb + (size_t)NMAX * 2;
    float* er0 = erb;                      float* er1 = erb + (size_t)NMAX * 2;

    float* out_hs = (float*)d_out;
    float* out_hp = (float*)d_out + (size_t)n * 64;

    const int EB = (e + 255) / 256;
    const int GB = (n + 127) / 128;
    const int WB = (n + 7) / 8;

    // 3 chunks, 128-aligned, each ≈ 1 full GPU wave of gemmF CTAs
    const int CH = ((n / 3 + 127) / 128) * 128;     // 16768
    int c0[3], cc[3];                               // chunk starts/counts
    c0[0] = 0;      cc[0] = CH;
    c0[1] = CH;     cc[1] = CH;
    c0[2] = 2 * CH; cc[2] = n - 2 * CH;

    constexpr int SMEM_F     = 2 * 128 * 384 + 256 * 384;
    constexpr int SMEM_SMALL = (128 + 128 + 64 + 64) * 64 * 2;
    cudaFuncSetAttribute(tc_gemm_fused<192>,    cudaFuncAttributeMaxDynamicSharedMemorySize, SMEM_F);
    cudaFuncSetAttribute(tc_gemm_small<64, 64>, cudaFuncAttributeMaxDynamicSharedMemorySize, SMEM_SMALL);

    static cudaStream_t s1 = nullptr, s2 = nullptr, s3 = nullptr;
    static cudaEvent_t evFork, evPrep, evCSR, evP0, evP1, evG0, evG1, evG2;
    static cudaEvent_t evA0[3], evA1[3], evEnd1, evEnd2;
    if (s1 == nullptr) {
        cudaStreamCreateWithFlags(&s1, cudaStreamNonBlocking);
        cudaStreamCreateWithFlags(&s2, cudaStreamNonBlocking);
        cudaStreamCreateWithFlags(&s3, cudaStreamNonBlocking);
        cudaEventCreateWithFlags(&evFork, cudaEventDisableTiming);
        cudaEventCreateWithFlags(&evPrep, cudaEventDisableTiming);
        cudaEventCreateWithFlags(&evCSR,  cudaEventDisableTiming);
        cudaEventCreateWithFlags(&evP0,   cudaEventDisableTiming);
        cudaEventCreateWithFlags(&evP1,   cudaEventDisableTiming);
        cudaEventCreateWithFlags(&evG0,   cudaEventDisableTiming);
        cudaEventCreateWithFlags(&evG1,   cudaEventDisableTiming);
        cudaEventCreateWithFlags(&evG2,   cudaEventDisableTiming);
        for (int i = 0; i < 3; i++) {
            cudaEventCreateWithFlags(&evA0[i], cudaEventDisableTiming);
            cudaEventCreateWithFlags(&evA1[i], cudaEventDisableTiming);
        }
        cudaEventCreateWithFlags(&evEnd1, cudaEventDisableTiming);
        cudaEventCreateWithFlags(&evEnd2, cudaEventDisableTiming);
    }

    Prep8 pa;
    const float* Ws[8] = {g0W, g0rW, g1W, g1rW, g2W, g2rW, p0W, p1W};
    for (int m = 0; m < 8; m++) {
        pa.W[m] = Ws[m];
        pa.K[m] = (m < 6) ? 192 : 64;
        pa.N[m] = (m < 6) ? 128 : 64;
        pa.off[m] = (m < 6) ? (m >> 1) * WT_FUSED + (m & 1) * (128 * 192)
                            : 3 * WT_FUSED + (m - 6) * WT_SMALL;
    }

    const int F0 = 0 * WT_FUSED, F1 = 1 * WT_FUSED, F2 = 2 * WT_FUSED;
    const int P0 = 3 * WT_FUSED, P1 = 3 * WT_FUSED + WT_SMALL;

    // ---- fork ----
    cudaEventRecord(evFork, 0);
    cudaStreamWaitEvent(s1, evFork, 0);
    cudaStreamWaitEvent(s2, evFork, 0);
    cudaStreamWaitEvent(s3, evFork, 0);

    prep_kernel<<<64, 256, 0, s1>>>(pa);
    cudaEventRecord(evPrep, s1);
    cudaStreamWaitEvent(s2, evPrep, 0);

    // s0: CSR build (hidden under prep + gemmF0)
    cudaMemsetAsync(cnt, 0, (size_t)n * sizeof(int), 0);
    count_kernel<<<EB, 256, 0, 0>>>(dst, e);
    scan_kernel<<<1, 1024, 0, 0>>>(n);
    fill_kernel<<<EB, 256, 0, 0>>>(src, dst, e);
    cudaEventRecord(evCSR, 0);

    // ---- layer 0 GEMMs (write buffer 0) ----
    tc_gemm_fused<192><<<GB, 256, SMEM_F, s1>>>(fvs, 128, pos, wthi + F0, wtlo + F0,
                                                g0al, g0ar, el0, er0, h0, rh0, n, 0);
    cudaEventRecord(evG0, s1);
    tc_gemm_small<64, 64><<<GB, 256, SMEM_SMALL, s2>>>(pos, wthi + P0, wtlo + P0,
                                                       p0al, p0ar, el2, er2, hq, n);
    cudaStreamWaitEvent(s2, evCSR, 0);
    agg_kernel<64, 1, false><<<WB, 256, 0, s2>>>(hq, pos, el2, er2, hp, 0, n);
    cudaEventRecord(evP0, s2);

    // ---- boundary 0: agg0 chunks on s3, gemmF1 chunks trail on s1 ----
    cudaStreamWaitEvent(s3, evCSR, 0);
    cudaStreamWaitEvent(s3, evG0, 0);
    for (int i = 0; i < 3; i++) {
        agg_kernel<128, 0, false><<<(cc[i] + 7) / 8, 256, 0, s3>>>(
            h0, rh0, el0, er0, hs, c0[i], cc[i]);
        cudaEventRecord(evA0[i], s3);
    }
    cudaStreamWaitEvent(s1, evP0, 0);          // gemmF1 needs hp
    for (int i = 0; i < 3; i++) {
        cudaStreamWaitEvent(s1, evA0[i], 0);   // chunk i of hs ready
        tc_gemm_fused<192><<<(cc[i] + 127) / 128, 256, SMEM_F, s1>>>(
            hs, 128, hp, wthi + F1, wtlo + F1,
            g1al, g1ar, el1, er1, h1, rh1, n, c0[i]);
    }
    cudaEventRecord(evG1, s1);

    // pg layer 1 (s2, overlaps boundary 0)
    tc_gemm_small<64, 64><<<GB, 256, SMEM_SMALL, s2>>>(hp, wthi + P1, wtlo + P1,
                                                       p1al, p1ar, el2, er2, hq, n);
    agg_kernel<64, 1, false><<<WB, 256, 0, s2>>>(hq, hp, el2, er2, out_hp, 0, n);
    cudaEventRecord(evP1, s2);

    // ---- boundary 1: agg1 chunks (read buf1, need ALL gemmF1 chunks) ----
    cudaStreamWaitEvent(s3, evG1, 0);
    for (int i = 0; i < 3; i++) {
        agg_kernel<128, 0, false><<<(cc[i] + 7) / 8, 256, 0, s3>>>(
            h1, rh1, el1, er1, hs2, c0[i], cc[i]);
        cudaEventRecord(evA1[i], s3);
    }
    cudaStreamWaitEvent(s1, evP1, 0);          // gemmF2 needs out_hp
    for (int i = 0; i < 3; i++) {
        cudaStreamWaitEvent(s1, evA1[i], 0);
        tc_gemm_fused<192><<<(cc[i] + 127) / 128, 256, SMEM_F, s1>>>(
            hs2, 128, out_hp, wthi + F2, wtlo + F2,
            g2al, g2ar, el0, er0, h0, rh0, n, c0[i]);
    }

    // ---- final agg (headmean; needs all gemmF2 chunks — stream order on s1) ----
    agg_kernel<128, 0, true><<<WB, 256, 0, s1>>>(h0, rh0, el0, er0, out_hs, 0, n);
    cudaEventRecord(evEnd1, s1);
    cudaEventRecord(evEnd2, s2);

    // ---- join ----
    cudaStreamWaitEvent(0, evEnd1, 0);
    cudaStreamWaitEvent(0, evEnd2, 0);
}